// round 14
// baseline (speedup 1.0000x reference)
#include <cuda_runtime.h>
#include <cuda_fp16.h>

// ---------------------------------------------------------------------------
// DeformableBottleneck: B=16, Cin=O=1024, H=W=32, P=256.
// All four convs as fp16 mma.sync GEMMs, fp32 accumulate.
// GEMM1 converts x fp32->fp16 in its loader (no pack_x pass).
// Offset conv: GEMM M=16384 N=32(18) K=2304, 64-row CTAs, grid 256.
// ---------------------------------------------------------------------------

#define HW 1024
#define CIN 1024
#define PDIM 256
#define ODIM 1024
#define BATCH 16
#define KT 32

typedef unsigned uns;
typedef unsigned short us;

__device__ us    g_hh [BATCH * HW * PDIM];          // h1 fp16, NHWC
__device__ us    g_h2h[BATCH * HW * PDIM];          // h2 fp16
__device__ float g_off[BATCH * 18 * HW];
__device__ us    g_Sh [BATCH * HW * 9 * PDIM];      // sampled im2col fp16
__device__ us    g_w1h[PDIM * CIN];
__device__ us    g_w2h[PDIM * 9 * PDIM];
__device__ us    g_w3h[ODIM * PDIM];
__device__ us    g_offwT[32 * 9 * PDIM];            // [j(pad32)][tap*256+c]
__device__ float g_s1[PDIM], g_t1[PDIM];
__device__ float g_s2[PDIM], g_t2[PDIM];
__device__ float g_s3[ODIM], g_t3[ODIM];

// main GEMM smem stage: A 0 (10240), B 10240 (20480)
#define OFF_B  10240
#define STAGE  30720
#define NSTAGE 3
#define SMEM_TOTAL (NSTAGE * STAGE)     // 92160 B

// off_gemm smem stage: A 0 (5120), B 5120 (2560)
#define OFF_OB  5120
#define OSTAGE  7680
#define OSMEM_TOTAL (4 * OSTAGE)        // 30720 B

// ------------------------- PTX helpers -------------------------
__device__ __forceinline__ uns smem_u32(const void* p) {
    uns r;
    asm("{ .reg .u64 t; cvta.to.shared.u64 t, %1; cvt.u32.u64 %0, t; }"
        : "=r"(r) : "l"(p));
    return r;
}
__device__ __forceinline__ void cpa(uns dst, const void* src) {
    asm volatile("cp.async.cg.shared.global [%0], [%1], 16;" :: "r"(dst), "l"(src) : "memory");
}
__device__ __forceinline__ void cpa_z(uns dst, const void* src, uns sz) {
    asm volatile("cp.async.cg.shared.global [%0], [%1], 16, %2;"
                 :: "r"(dst), "l"(src), "r"(sz) : "memory");
}
__device__ __forceinline__ void cpa_commit() {
    asm volatile("cp.async.commit_group;" ::: "memory");
}
template <int N> __device__ __forceinline__ void cpa_wait() {
    asm volatile("cp.async.wait_group %0;" :: "n"(N) : "memory");
}
__device__ __forceinline__ void ldsm4(uns* r, uns a) {
    asm volatile("ldmatrix.sync.aligned.m8n8.x4.shared.b16 {%0,%1,%2,%3}, [%4];"
                 : "=r"(r[0]), "=r"(r[1]), "=r"(r[2]), "=r"(r[3]) : "r"(a));
}
__device__ __forceinline__ void ldsm4t(uns* r, uns a) {
    asm volatile("ldmatrix.sync.aligned.m8n8.x4.trans.shared.b16 {%0,%1,%2,%3}, [%4];"
                 : "=r"(r[0]), "=r"(r[1]), "=r"(r[2]), "=r"(r[3]) : "r"(a));
}
__device__ __forceinline__ void mma_f16(float* d, const uns* a, const uns* b) {
    asm volatile(
        "mma.sync.aligned.m16n8k16.row.col.f32.f16.f16.f32 "
        "{%0,%1,%2,%3}, {%4,%5,%6,%7}, {%8,%9}, {%0,%1,%2,%3};"
        : "+f"(d[0]), "+f"(d[1]), "+f"(d[2]), "+f"(d[3])
        : "r"(a[0]), "r"(a[1]), "r"(a[2]), "r"(a[3]), "r"(b[0]), "r"(b[1]));
}
__device__ __forceinline__ us f2h(float x) {
    return __half_as_ushort(__float2half_rn(x));
}
__device__ __forceinline__ uns pack2h(float a, float b) {
    __half2 h = __floats2half2_rn(a, b);
    return *(uns*)&h;
}

// ------------------------- merged prep kernel -------------------------
// blocks [0,288): pack_offwT; [288,2592): pack_w2; [2592,2848): w1;
// [2848,3104): w3; [3104,3108): bnprep
__global__ void prep_kernel(const float* __restrict__ off_w,
                            const float* __restrict__ w2,
                            const float* __restrict__ w1,
                            const float* __restrict__ w3,
                            const float* __restrict__ g1, const float* __restrict__ b1,
                            const float* __restrict__ m1, const float* __restrict__ v1,
                            const float* __restrict__ g2, const float* __restrict__ b2,
                            const float* __restrict__ m2, const float* __restrict__ v2,
                            const float* __restrict__ g3, const float* __restrict__ b3,
                            const float* __restrict__ m3, const float* __restrict__ v3) {
    int blk = blockIdx.x;
    int tid = threadIdx.x;
    if (blk < 288) {
        int idx = blk * 256 + tid;                  // < 32*2304
        int j = idx / 2304;
        int r = idx % 2304;
        int tap = r >> 8;
        int c = r & 255;
        g_offwT[idx] = (j < 18) ? f2h(off_w[(j * 256 + c) * 9 + tap]) : (us)0;
    } else if (blk < 2592) {
        int idx = (blk - 288) * 256 + tid;          // < 256*2304
        int o = idx / 2304;
        int r = idx % 2304;
        int k = r >> 8;
        int c = r & 255;
        g_w2h[idx] = f2h(w2[(o * 256 + c) * 9 + k]);
    } else if (blk < 2848) {
        int i = (blk - 2592) * 256 + tid;           // < 65536 float4s
        float4 v = ((const float4*)w1)[i];
        ((ushort4*)g_w1h)[i] = make_ushort4(f2h(v.x), f2h(v.y), f2h(v.z), f2h(v.w));
    } else if (blk < 3104) {
        int i = (blk - 2848) * 256 + tid;
        float4 v = ((const float4*)w3)[i];
        ((ushort4*)g_w3h)[i] = make_ushort4(f2h(v.x), f2h(v.y), f2h(v.z), f2h(v.w));
    } else {
        int i = (blk - 3104) * 256 + tid;
        if (i < PDIM) {
            float s = g1[i] / sqrtf(v1[i] + 1e-5f);
            g_s1[i] = s; g_t1[i] = b1[i] - m1[i] * s;
            s = g2[i] / sqrtf(v2[i] + 1e-5f);
            g_s2[i] = s; g_t2[i] = b2[i] - m2[i] * s;
        }
        if (i < ODIM) {
            float s = g3[i] / sqrtf(v3[i] + 1e-5f);
            g_s3[i] = s; g_t3[i] = b3[i] - m3[i] * s;
        }
    }
}

// ------------------------- main tensor-core GEMM -------------------------
// CTA 128x256 full-N. MODE 1: A=x fp32 (k-major per batch, cvt in loader), B=w1 -> g_hh
// MODE 2: A=g_Sh [m][2304], B=w2t -> g_h2h
// MODE 3: A=g_h2h [m][256], B=w3 n-tile(256) -> OUT NCHW, grid (128,4)
template <int MODE>
__global__ void __launch_bounds__(512, 1) tc_gemm(const float* __restrict__ Xres,
                                                  float* __restrict__ Out) {
    extern __shared__ char ds[];
    constexpr int Ktot = (MODE == 1) ? 1024 : (MODE == 2) ? 2304 : 256;
    constexpr int T = Ktot / KT;

    const int tid = threadIdx.x;
    const int lane = tid & 31;
    const int wid = tid >> 5;
    const int g = lane >> 2;
    const int tq = lane & 3;
    const int mw = wid & 3;          // 4 m groups of 32 rows
    const int nw = wid >> 2;         // 4 n groups of 64 cols
    const int n0 = (MODE == 3) ? blockIdx.y * 256 : 0;

    const us *Ah_g = nullptr, *Bh_g;
    const float* Xf = nullptr;       // MODE 1: fp32 source
    int m0 = 0, b_img = 0, hw0 = 0;
    if constexpr (MODE == 1) {
        b_img = blockIdx.x >> 3;
        hw0 = (blockIdx.x & 7) << 7;
        Xf = Xres + (size_t)b_img * (CIN * HW);
        Bh_g = g_w1h;
    } else if constexpr (MODE == 2) {
        m0 = blockIdx.x * 128;
        Ah_g = g_Sh;
        Bh_g = g_w2h;
    } else {
        m0 = blockIdx.x * 128;
        Ah_g = g_h2h;
        Bh_g = g_w3h + (size_t)n0 * Ktot;
    }

    const uns sb = smem_u32(ds);

    auto issueB = [&](int t) {
        const int k0 = t * KT;
        const uns st = sb + (t % NSTAGE) * STAGE;
#pragma unroll
        for (int r = 0; r < 2; r++) {
            int i = tid + 512 * r;
            int row = i >> 2, c = i & 3;
            const us* sh = Bh_g + (size_t)row * Ktot + k0 + c * 8;
            cpa(st + OFF_B + row * 80 + c * 16, sh);
        }
        if constexpr (MODE != 1) {
            int row = tid >> 2, c = tid & 3;      // 128 m-rows x 4 chunks
            const us* sh = Ah_g + (size_t)(m0 + row) * Ktot + k0 + c * 8;
            cpa(st + row * 80 + c * 16, sh);
        }
        cpa_commit();
    };
    // MODE 1 only: synchronous fp32 load + cvt + STS of A tile
    auto buildA = [&](int t) {
        if constexpr (MODE == 1) {
            const int k0 = t * KT;
            const uns st = sb + (t % NSTAGE) * STAGE;
            int row = tid >> 4, c = tid & 15;     // 32 k-rows x 16 chunks of 8
            const float* src = Xf + (size_t)(k0 + row) * HW + hw0 + c * 8;
            float4 a = *(const float4*)(src);
            float4 b = *(const float4*)(src + 4);
            uint4 o;
            o.x = pack2h(a.x, a.y);
            o.y = pack2h(a.z, a.w);
            o.z = pack2h(b.x, b.y);
            o.w = pack2h(b.z, b.w);
            *(uint4*)(ds + (st - sb) + row * 272 + c * 16) = o;
        }
    };

    float acc[2][8][4];
#pragma unroll
    for (int i = 0; i < 2; i++)
#pragma unroll
        for (int j = 0; j < 8; j++)
#pragma unroll
            for (int c = 0; c < 4; c++) acc[i][j][c] = 0.0f;

    const int aRow  = (lane & 7) + ((lane >> 3) & 1) * 8;
    const int aColB = (lane >> 4) * 16;
    const int tRow  = (lane & 7) + ((lane >> 4) & 1) * 8;
    const int tColB = ((lane >> 3) & 1) * 16;

    issueB(0); issueB(1);
    buildA(0); buildA(1);

    for (int t = 0; t < T; t++) {
        cpa_wait<1>();
        __syncthreads();
        if (t + 2 < T) { issueB(t + 2); buildA(t + 2); }
        else cpa_commit();
        const uns st = sb + (t % NSTAGE) * STAGE;
#pragma unroll
        for (int kk = 0; kk < 2; kk++) {
            uns ah[2][4], bh[8][2];
#pragma unroll
            for (int mt = 0; mt < 2; mt++) {
                if constexpr (MODE == 1) {
                    uns addr = st + (kk * 16 + tRow) * 272 + (mw * 32 + mt * 16) * 2 + tColB;
                    ldsm4t(ah[mt], addr);
                } else {
                    uns addr = st + (mw * 32 + mt * 16 + aRow) * 80 + kk * 32 + aColB;
                    ldsm4(ah[mt], addr);
                }
            }
#pragma unroll
            for (int p = 0; p < 4; p++) {
                uns r4[4];
                uns addr = st + OFF_B + (nw * 64 + p * 16 + aRow) * 80 + kk * 32 + aColB;
                ldsm4(r4, addr);
                bh[2 * p][0] = r4[0]; bh[2 * p + 1][0] = r4[1];
                bh[2 * p][1] = r4[2]; bh[2 * p + 1][1] = r4[3];
            }
#pragma unroll
            for (int mt = 0; mt < 2; mt++)
#pragma unroll
                for (int nt = 0; nt < 8; nt++)
                    mma_f16(acc[mt][nt], ah[mt], bh[nt]);
        }
    }

    // ---------------- epilogue ----------------
    if constexpr (MODE == 3) {
        float* Cs = (float*)ds;   // [128 n][132]
        int bb = m0 >> 10;
        int hwb = m0 & 1023;
        size_t obase = ((size_t)bb << 20) + hwb;
#pragma unroll
        for (int half = 0; half < 2; half++) {
            __syncthreads();
            if ((nw >> 1) == half) {
                int colbase = (nw & 1) * 64;
#pragma unroll
                for (int mt = 0; mt < 2; mt++) {
#pragma unroll
                    for (int nt = 0; nt < 8; nt++) {
                        int row = mw * 32 + mt * 16 + g;
                        int col = colbase + nt * 8 + 2 * tq;
                        Cs[(col)     * 132 + row]     = acc[mt][nt][0];
                        Cs[(col + 1) * 132 + row]     = acc[mt][nt][1];
                        Cs[(col)     * 132 + row + 8] = acc[mt][nt][2];
                        Cs[(col + 1) * 132 + row + 8] = acc[mt][nt][3];
                    }
                }
            }
            __syncthreads();
#pragma unroll
            for (int i = 0; i < 32; i++) {
                int idx = i * 512 + tid;
                int nl = idx >> 7;
                int ml = idx & 127;
                int n = n0 + half * 128 + nl;
                float v = fmaf(Cs[nl * 132 + ml], g_s3[n], g_t3[n]);
                size_t addr = obase + ((size_t)n << 10) + ml;
                v += Xres[addr];
                Out[addr] = fmaxf(v, 0.0f);
            }
        }
    } else {
        us* dh;
        const float *sc, *tc;
        if constexpr (MODE == 1) {
            dh = g_hh + ((size_t)((b_img << 10) + hw0)) * 256;
            sc = g_s1; tc = g_t1;
        } else {
            dh = g_h2h + (size_t)m0 * 256;
            sc = g_s2; tc = g_t2;
        }
#pragma unroll
        for (int mt = 0; mt < 2; mt++) {
#pragma unroll
            for (int nt = 0; nt < 8; nt++) {
                int row = mw * 32 + mt * 16 + g;
                int col = nw * 64 + nt * 8 + 2 * tq;
                float s0 = sc[col], t0 = tc[col];
                float s1 = sc[col + 1], t1 = tc[col + 1];
                float v0 = fmaxf(fmaf(acc[mt][nt][0], s0, t0), 0.0f);
                float v1 = fmaxf(fmaf(acc[mt][nt][1], s1, t1), 0.0f);
                float v2 = fmaxf(fmaf(acc[mt][nt][2], s0, t0), 0.0f);
                float v3 = fmaxf(fmaf(acc[mt][nt][3], s1, t1), 0.0f);
                *(uns*)(dh + (size_t)row * 256 + col) = (uns)f2h(v0) | ((uns)f2h(v1) << 16);
                *(uns*)(dh + (size_t)(row + 8) * 256 + col) = (uns)f2h(v2) | ((uns)f2h(v3) << 16);
            }
        }
    }
}

// ------------------------- offset conv as GEMM -------------------------
// C[m=16384][n=32(18)] = im2col(h)[m][k=2304] @ offwT[n][k]
// 128 threads (4 warps x 16 m-rows), 64-row CTAs, grid 256.
__global__ void __launch_bounds__(128, 4) off_gemm(const float* __restrict__ off_b) {
    extern __shared__ char ds[];
    const int tid = threadIdx.x;
    const int lane = tid & 31;
    const int wid = tid >> 5;
    const int g = lane >> 2;
    const int tq = lane & 3;
    const int m0 = blockIdx.x * 64;
    const int b_img = m0 >> 10;
    const int hw0 = m0 & 1023;
    const uns sb = smem_u32(ds);

    auto issue = [&](int t) {
        const int k0 = t * KT;
        const int tap = k0 >> 8;
        const int c0 = k0 & 255;
        const int dy = tap / 3 - 1, dx = tap % 3 - 1;
        const uns st = sb + (t & 3) * OSTAGE;
        {
            int row = tid >> 2, c = tid & 3;      // 32 n-rows x 4 chunks
            const us* src = g_offwT + row * 2304 + k0 + c * 8;
            cpa(st + OFF_OB + row * 80 + c * 16, src);
        }
#pragma unroll
        for (int r = 0; r < 2; r++) {
            int i = tid + 128 * r;
            int row = i >> 2, c = i & 3;          // 64 m-rows x 4 chunks
            int hw = hw0 + row;
            int y = hw >> 5, x = hw & 31;
            int yy = y + dy, xx = x + dx;
            uns ok = (yy >= 0 && yy < 32 && xx >= 0 && xx < 32) ? 16u : 0u;
            int yc = min(max(yy, 0), 31), xc = min(max(xx, 0), 31);
            const us* src = g_hh + ((size_t)((b_img << 10) + (yc << 5) + xc)) * 256 + c0 + c * 8;
            cpa_z(st + row * 80 + c * 16, src, ok);
        }
        cpa_commit();
    };

    float acc[4][4];
#pragma unroll
    for (int j = 0; j < 4; j++)
#pragma unroll
        for (int c = 0; c < 4; c++) acc[j][c] = 0.0f;

    const int aRow  = (lane & 7) + ((lane >> 3) & 1) * 8;
    const int aColB = (lane >> 4) * 16;

    issue(0); issue(1); issue(2);

    const int T = 2304 / KT;   // 72
    for (int t = 0; t < T; t++) {
        cpa_wait<2>();
        __syncthreads();
        if (t + 3 < T) issue(t + 3); else cpa_commit();
        const uns st = sb + (t & 3) * OSTAGE;
#pragma unroll
        for (int kk = 0; kk < 2; kk++) {
            uns ah[4], bh[4][2];
            {
                uns addr = st + (wid * 16 + aRow) * 80 + kk * 32 + aColB;
                ldsm4(ah, addr);
            }
#pragma unroll
            for (int p = 0; p < 2; p++) {
                uns r4[4];
                uns addr = st + OFF_OB + (p * 16 + aRow) * 80 + kk * 32 + aColB;
                ldsm4(r4, addr);
                bh[2 * p][0] = r4[0]; bh[2 * p + 1][0] = r4[1];
                bh[2 * p][1] = r4[2]; bh[2 * p + 1][1] = r4[3];
            }
#pragma unroll
            for (int nt = 0; nt < 4; nt++)
                mma_f16(acc[nt], ah, bh[nt]);
        }
        __syncthreads();
    }

    // epilogue: offsets for n<18, + bias
    float* dst = g_off + (size_t)b_img * (18 * HW) + hw0;
#pragma unroll
    for (int nt = 0; nt < 4; nt++) {
        int col = nt * 8 + 2 * tq;
        int row = wid * 16 + g;
        if (col < 18) {
            float bb = off_b[col];
            dst[col * HW + row] = acc[nt][0] + bb;
            dst[col * HW + row + 8] = acc[nt][2] + bb;
        }
        if (col + 1 < 18) {
            float bb = off_b[col + 1];
            dst[(col + 1) * HW + row] = acc[nt][1] + bb;
            dst[(col + 1) * HW + row + 8] = acc[nt][3] + bb;
        }
    }
}

// ------------------------- bilinear sampler -------------------------
__global__ void sampler_kernel() {
    int gi = blockIdx.x * 8 + (threadIdx.x >> 5);
    int lane = threadIdx.x & 31;
    int k = gi % 9;
    int t = gi / 9;
    int hw = t & 1023;
    int b = t >> 10;
    int y = hw >> 5, xx = hw & 31;

    const float* offp = g_off + b * (18 * HW) + (2 * k) * HW + hw;
    float oy = offp[0];
    float ox = offp[HW];
    float py = (float)(y + k / 3 - 1) + oy;
    float px = (float)(xx + k % 3 - 1) + ox;
    float y0f = floorf(py), x0f = floorf(px);
    float wy = py - y0f, wx = px - x0f;
    int y0 = (int)y0f, x0 = (int)x0f;
    int y1 = y0 + 1, x1 = x0 + 1;
    float vy0 = (y0 >= 0 && y0 <= 31) ? 1.0f : 0.0f;
    float vy1 = (y1 >= 0 && y1 <= 31) ? 1.0f : 0.0f;
    float vx0 = (x0 >= 0 && x0 <= 31) ? 1.0f : 0.0f;
    float vx1 = (x1 >= 0 && x1 <= 31) ? 1.0f : 0.0f;
    float wgt[4];
    wgt[0] = (1.0f - wy) * (1.0f - wx) * vy0 * vx0;
    wgt[1] = (1.0f - wy) * wx * vy0 * vx1;
    wgt[2] = wy * (1.0f - wx) * vy1 * vx0;
    wgt[3] = wy * wx * vy1 * vx1;
    int y0c = min(max(y0, 0), 31), y1c = min(max(y1, 0), 31);
    int x0c = min(max(x0, 0), 31), x1c = min(max(x1, 0), 31);

    const us* hh = g_hh + (size_t)b * (HW * PDIM);
    int ci[4];
    ci[0] = (y0c * 32 + x0c) * PDIM;
    ci[1] = (y0c * 32 + x1c) * PDIM;
    ci[2] = (y1c * 32 + x0c) * PDIM;
    ci[3] = (y1c * 32 + x1c) * PDIM;

    const int c = lane * 8;
    uint4 Hq[4];
#pragma unroll
    for (int q = 0; q < 4; q++)
        Hq[q] = *(const uint4*)(hh + ci[q] + c);

    uns oh[4];
#pragma unroll
    for (int wi = 0; wi < 4; wi++) {
        float ax = 0.0f, ay = 0.0f;
#pragma unroll
        for (int q = 0; q < 4; q++) {
            __half2 hu = *(const __half2*)&((const uns*)&Hq[q])[wi];
            float2 vh = __half22float2(hu);
            ax = fmaf(wgt[q], vh.x, ax);
            ay = fmaf(wgt[q], vh.y, ay);
        }
        oh[wi] = (uns)f2h(ax) | ((uns)f2h(ay) << 16);
    }
    size_t dbase = ((size_t)t * 9 + k) * PDIM + c;
    *(uint4*)(g_Sh + dbase) = make_uint4(oh[0], oh[1], oh[2], oh[3]);
}

// ------------------------- launcher -------------------------
extern "C" void kernel_launch(void* const* d_in, const int* in_sizes, int n_in,
                              void* d_out, int out_size) {
    const float* x     = (const float*)d_in[0];
    const float* w1    = (const float*)d_in[1];
    const float* bn1g  = (const float*)d_in[2];
    const float* bn1b  = (const float*)d_in[3];
    const float* bn1m  = (const float*)d_in[4];
    const float* bn1v  = (const float*)d_in[5];
    const float* off_w = (const float*)d_in[6];
    const float* off_b = (const float*)d_in[7];
    const float* w2    = (const float*)d_in[8];
    const float* bn2g  = (const float*)d_in[9];
    const float* bn2b  = (const float*)d_in[10];
    const float* bn2m  = (const float*)d_in[11];
    const float* bn2v  = (const float*)d_in[12];
    const float* w3    = (const float*)d_in[13];
    const float* bn3g  = (const float*)d_in[14];
    const float* bn3b  = (const float*)d_in[15];
    const float* bn3m  = (const float*)d_in[16];
    const float* bn3v  = (const float*)d_in[17];
    float* out = (float*)d_out;

    cudaFuncSetAttribute(tc_gemm<1>, cudaFuncAttributeMaxDynamicSharedMemorySize, SMEM_TOTAL);
    cudaFuncSetAttribute(tc_gemm<2>, cudaFuncAttributeMaxDynamicSharedMemorySize, SMEM_TOTAL);
    cudaFuncSetAttribute(tc_gemm<3>, cudaFuncAttributeMaxDynamicSharedMemorySize, SMEM_TOTAL);
    cudaFuncSetAttribute(off_gemm, cudaFuncAttributeMaxDynamicSharedMemorySize, OSMEM_TOTAL);

    prep_kernel<<<3108, 256>>>(off_w, w2, w1, w3,
                               bn1g, bn1b, bn1m, bn1v,
                               bn2g, bn2b, bn2m, bn2v,
                               bn3g, bn3b, bn3m, bn3v);
    tc_gemm<1><<<128, 512, SMEM_TOTAL>>>(x, nullptr);
    off_gemm<<<256, 128, OSMEM_TOTAL>>>(off_b);
    sampler_kernel<<<18432, 256>>>();             // 4th launch: ncu slot
    tc_gemm<2><<<128, 512, SMEM_TOTAL>>>(nullptr, nullptr);
    tc_gemm<3><<<dim3(128, 4), 512, SMEM_TOTAL>>>(x, out);
}

// round 15
// speedup vs baseline: 1.0641x; 1.0641x over previous
#include <cuda_runtime.h>
#include <cuda_fp16.h>

// ---------------------------------------------------------------------------
// DeformableBottleneck: B=16, Cin=O=1024, H=W=32, P=256.
// All convs as fp16 mma.sync GEMMs, fp32 accumulate.
// GEMM2 fuses bilinear sampling into its A-loader (no S buffer, no sampler).
// ---------------------------------------------------------------------------

#define HW 1024
#define CIN 1024
#define PDIM 256
#define ODIM 1024
#define BATCH 16
#define KT 32

typedef unsigned uns;
typedef unsigned short us;

__device__ us    g_hh [BATCH * HW * PDIM];          // h1 fp16, NHWC
__device__ us    g_h2h[BATCH * HW * PDIM];          // h2 fp16
__device__ float g_off[BATCH * 18 * HW];
__device__ us    g_w1h[PDIM * CIN];
__device__ us    g_w2h[PDIM * 9 * PDIM];
__device__ us    g_w3h[ODIM * PDIM];
__device__ us    g_offwT[32 * 9 * PDIM];            // [j(pad32)][tap*256+c]
__device__ float g_s1[PDIM], g_t1[PDIM];
__device__ float g_s2[PDIM], g_t2[PDIM];
__device__ float g_s3[ODIM], g_t3[ODIM];

// main GEMM smem stage: A 0 (10240), B 10240 (20480)
#define OFF_B  10240
#define STAGE  30720
#define NSTAGE 3
#define SMEM_TOTAL (NSTAGE * STAGE)     // 92160 B

// fused GEMM2: + persistent sampling table
#define P_W (3 * STAGE)                 // 92160: 1152 * float4
#define P_I (P_W + 18432)               // 110592: 1152 * ushort4
#define SMEM2_TOTAL (P_I + 9216)        // 119808 B

// off_gemm smem stage: A 0 (5120), B 5120 (2560)
#define OFF_OB  5120
#define OSTAGE  7680
#define OSMEM_TOTAL (4 * OSTAGE)        // 30720 B

// ------------------------- PTX helpers -------------------------
__device__ __forceinline__ uns smem_u32(const void* p) {
    uns r;
    asm("{ .reg .u64 t; cvta.to.shared.u64 t, %1; cvt.u32.u64 %0, t; }"
        : "=r"(r) : "l"(p));
    return r;
}
__device__ __forceinline__ void cpa(uns dst, const void* src) {
    asm volatile("cp.async.cg.shared.global [%0], [%1], 16;" :: "r"(dst), "l"(src) : "memory");
}
__device__ __forceinline__ void cpa_z(uns dst, const void* src, uns sz) {
    asm volatile("cp.async.cg.shared.global [%0], [%1], 16, %2;"
                 :: "r"(dst), "l"(src), "r"(sz) : "memory");
}
__device__ __forceinline__ void cpa_commit() {
    asm volatile("cp.async.commit_group;" ::: "memory");
}
template <int N> __device__ __forceinline__ void cpa_wait() {
    asm volatile("cp.async.wait_group %0;" :: "n"(N) : "memory");
}
__device__ __forceinline__ void ldsm4(uns* r, uns a) {
    asm volatile("ldmatrix.sync.aligned.m8n8.x4.shared.b16 {%0,%1,%2,%3}, [%4];"
                 : "=r"(r[0]), "=r"(r[1]), "=r"(r[2]), "=r"(r[3]) : "r"(a));
}
__device__ __forceinline__ void ldsm4t(uns* r, uns a) {
    asm volatile("ldmatrix.sync.aligned.m8n8.x4.trans.shared.b16 {%0,%1,%2,%3}, [%4];"
                 : "=r"(r[0]), "=r"(r[1]), "=r"(r[2]), "=r"(r[3]) : "r"(a));
}
__device__ __forceinline__ void mma_f16(float* d, const uns* a, const uns* b) {
    asm volatile(
        "mma.sync.aligned.m16n8k16.row.col.f32.f16.f16.f32 "
        "{%0,%1,%2,%3}, {%4,%5,%6,%7}, {%8,%9}, {%0,%1,%2,%3};"
        : "+f"(d[0]), "+f"(d[1]), "+f"(d[2]), "+f"(d[3])
        : "r"(a[0]), "r"(a[1]), "r"(a[2]), "r"(a[3]), "r"(b[0]), "r"(b[1]));
}
__device__ __forceinline__ us f2h(float x) {
    return __half_as_ushort(__float2half_rn(x));
}
__device__ __forceinline__ uns pack2h(float a, float b) {
    __half2 h = __floats2half2_rn(a, b);
    return *(uns*)&h;
}

// ------------------------- merged prep kernel -------------------------
__global__ void prep_kernel(const float* __restrict__ off_w,
                            const float* __restrict__ w2,
                            const float* __restrict__ w1,
                            const float* __restrict__ w3,
                            const float* __restrict__ g1, const float* __restrict__ b1,
                            const float* __restrict__ m1, const float* __restrict__ v1,
                            const float* __restrict__ g2, const float* __restrict__ b2,
                            const float* __restrict__ m2, const float* __restrict__ v2,
                            const float* __restrict__ g3, const float* __restrict__ b3,
                            const float* __restrict__ m3, const float* __restrict__ v3) {
    int blk = blockIdx.x;
    int tid = threadIdx.x;
    if (blk < 288) {
        int idx = blk * 256 + tid;                  // < 32*2304
        int j = idx / 2304;
        int r = idx % 2304;
        int tap = r >> 8;
        int c = r & 255;
        g_offwT[idx] = (j < 18) ? f2h(off_w[(j * 256 + c) * 9 + tap]) : (us)0;
    } else if (blk < 2592) {
        int idx = (blk - 288) * 256 + tid;          // < 256*2304
        int o = idx / 2304;
        int r = idx % 2304;
        int k = r >> 8;
        int c = r & 255;
        g_w2h[idx] = f2h(w2[(o * 256 + c) * 9 + k]);
    } else if (blk < 2848) {
        int i = (blk - 2592) * 256 + tid;           // < 65536 float4s
        float4 v = ((const float4*)w1)[i];
        ((ushort4*)g_w1h)[i] = make_ushort4(f2h(v.x), f2h(v.y), f2h(v.z), f2h(v.w));
    } else if (blk < 3104) {
        int i = (blk - 2848) * 256 + tid;
        float4 v = ((const float4*)w3)[i];
        ((ushort4*)g_w3h)[i] = make_ushort4(f2h(v.x), f2h(v.y), f2h(v.z), f2h(v.w));
    } else {
        int i = (blk - 3104) * 256 + tid;
        if (i < PDIM) {
            float s = g1[i] / sqrtf(v1[i] + 1e-5f);
            g_s1[i] = s; g_t1[i] = b1[i] - m1[i] * s;
            s = g2[i] / sqrtf(v2[i] + 1e-5f);
            g_s2[i] = s; g_t2[i] = b2[i] - m2[i] * s;
        }
        if (i < ODIM) {
            float s = g3[i] / sqrtf(v3[i] + 1e-5f);
            g_s3[i] = s; g_t3[i] = b3[i] - m3[i] * s;
        }
    }
}

// ------------------------- main tensor-core GEMM (modes 1, 3) ----------------
template <int MODE>
__global__ void __launch_bounds__(512, 1) tc_gemm(const float* __restrict__ Xres,
                                                  float* __restrict__ Out) {
    extern __shared__ char ds[];
    constexpr int Ktot = (MODE == 1) ? 1024 : 256;
    constexpr int T = Ktot / KT;

    const int tid = threadIdx.x;
    const int lane = tid & 31;
    const int wid = tid >> 5;
    const int g = lane >> 2;
    const int tq = lane & 3;
    const int mw = wid & 3;
    const int nw = wid >> 2;
    const int n0 = (MODE == 3) ? blockIdx.y * 256 : 0;

    const us *Ah_g = nullptr, *Bh_g;
    const float* Xf = nullptr;
    int m0 = 0, b_img = 0, hw0 = 0;
    if constexpr (MODE == 1) {
        b_img = blockIdx.x >> 3;
        hw0 = (blockIdx.x & 7) << 7;
        Xf = Xres + (size_t)b_img * (CIN * HW);
        Bh_g = g_w1h;
    } else {
        m0 = blockIdx.x * 128;
        Ah_g = g_h2h;
        Bh_g = g_w3h + (size_t)n0 * Ktot;
    }

    const uns sb = smem_u32(ds);

    auto issueB = [&](int t) {
        const int k0 = t * KT;
        const uns st = sb + (t % NSTAGE) * STAGE;
#pragma unroll
        for (int r = 0; r < 2; r++) {
            int i = tid + 512 * r;
            int row = i >> 2, c = i & 3;
            const us* sh = Bh_g + (size_t)row * Ktot + k0 + c * 8;
            cpa(st + OFF_B + row * 80 + c * 16, sh);
        }
        if constexpr (MODE != 1) {
            int row = tid >> 2, c = tid & 3;
            const us* sh = Ah_g + (size_t)(m0 + row) * Ktot + k0 + c * 8;
            cpa(st + row * 80 + c * 16, sh);
        }
        cpa_commit();
    };
    auto buildA = [&](int t) {
        if constexpr (MODE == 1) {
            const int k0 = t * KT;
            const uns st = sb + (t % NSTAGE) * STAGE;
            int row = tid >> 4, c = tid & 15;
            const float* src = Xf + (size_t)(k0 + row) * HW + hw0 + c * 8;
            float4 a = *(const float4*)(src);
            float4 b = *(const float4*)(src + 4);
            uint4 o;
            o.x = pack2h(a.x, a.y);
            o.y = pack2h(a.z, a.w);
            o.z = pack2h(b.x, b.y);
            o.w = pack2h(b.z, b.w);
            *(uint4*)(ds + (st - sb) + row * 272 + c * 16) = o;
        }
    };

    float acc[2][8][4];
#pragma unroll
    for (int i = 0; i < 2; i++)
#pragma unroll
        for (int j = 0; j < 8; j++)
#pragma unroll
            for (int c = 0; c < 4; c++) acc[i][j][c] = 0.0f;

    const int aRow  = (lane & 7) + ((lane >> 3) & 1) * 8;
    const int aColB = (lane >> 4) * 16;
    const int tRow  = (lane & 7) + ((lane >> 4) & 1) * 8;
    const int tColB = ((lane >> 3) & 1) * 16;

    issueB(0); issueB(1);
    buildA(0); buildA(1);

    for (int t = 0; t < T; t++) {
        cpa_wait<1>();
        __syncthreads();
        if (t + 2 < T) { issueB(t + 2); buildA(t + 2); }
        else cpa_commit();
        const uns st = sb + (t % NSTAGE) * STAGE;
#pragma unroll
        for (int kk = 0; kk < 2; kk++) {
            uns ah[2][4], bh[8][2];
#pragma unroll
            for (int mt = 0; mt < 2; mt++) {
                if constexpr (MODE == 1) {
                    uns addr = st + (kk * 16 + tRow) * 272 + (mw * 32 + mt * 16) * 2 + tColB;
                    ldsm4t(ah[mt], addr);
                } else {
                    uns addr = st + (mw * 32 + mt * 16 + aRow) * 80 + kk * 32 + aColB;
                    ldsm4(ah[mt], addr);
                }
            }
#pragma unroll
            for (int p = 0; p < 4; p++) {
                uns r4[4];
                uns addr = st + OFF_B + (nw * 64 + p * 16 + aRow) * 80 + kk * 32 + aColB;
                ldsm4(r4, addr);
                bh[2 * p][0] = r4[0]; bh[2 * p + 1][0] = r4[1];
                bh[2 * p][1] = r4[2]; bh[2 * p + 1][1] = r4[3];
            }
#pragma unroll
            for (int mt = 0; mt < 2; mt++)
#pragma unroll
                for (int nt = 0; nt < 8; nt++)
                    mma_f16(acc[mt][nt], ah[mt], bh[nt]);
        }
    }

    // ---------------- epilogue ----------------
    if constexpr (MODE == 3) {
        float* Cs = (float*)ds;   // [128 n][132]
        int bb = m0 >> 10;
        int hwb = m0 & 1023;
        size_t obase = ((size_t)bb << 20) + hwb;
#pragma unroll
        for (int half = 0; half < 2; half++) {
            __syncthreads();
            if ((nw >> 1) == half) {
                int colbase = (nw & 1) * 64;
#pragma unroll
                for (int mt = 0; mt < 2; mt++) {
#pragma unroll
                    for (int nt = 0; nt < 8; nt++) {
                        int row = mw * 32 + mt * 16 + g;
                        int col = colbase + nt * 8 + 2 * tq;
                        Cs[(col)     * 132 + row]     = acc[mt][nt][0];
                        Cs[(col + 1) * 132 + row]     = acc[mt][nt][1];
                        Cs[(col)     * 132 + row + 8] = acc[mt][nt][2];
                        Cs[(col + 1) * 132 + row + 8] = acc[mt][nt][3];
                    }
                }
            }
            __syncthreads();
#pragma unroll
            for (int i = 0; i < 32; i++) {
                int idx = i * 512 + tid;
                int nl = idx >> 7;
                int ml = idx & 127;
                int n = n0 + half * 128 + nl;
                float v = fmaf(Cs[nl * 132 + ml], g_s3[n], g_t3[n]);
                size_t addr = obase + ((size_t)n << 10) + ml;
                v += Xres[addr];
                Out[addr] = fmaxf(v, 0.0f);
            }
        }
    } else {
        us* dh = g_hh + ((size_t)((b_img << 10) + hw0)) * 256;
#pragma unroll
        for (int mt = 0; mt < 2; mt++) {
#pragma unroll
            for (int nt = 0; nt < 8; nt++) {
                int row = mw * 32 + mt * 16 + g;
                int col = nw * 64 + nt * 8 + 2 * tq;
                float s0 = g_s1[col], t0 = g_t1[col];
                float s1 = g_s1[col + 1], t1 = g_t1[col + 1];
                float v0 = fmaxf(fmaf(acc[mt][nt][0], s0, t0), 0.0f);
                float v1 = fmaxf(fmaf(acc[mt][nt][1], s1, t1), 0.0f);
                float v2 = fmaxf(fmaf(acc[mt][nt][2], s0, t0), 0.0f);
                float v3 = fmaxf(fmaf(acc[mt][nt][3], s1, t1), 0.0f);
                *(uns*)(dh + (size_t)row * 256 + col) = (uns)f2h(v0) | ((uns)f2h(v1) << 16);
                *(uns*)(dh + (size_t)(row + 8) * 256 + col) = (uns)f2h(v2) | ((uns)f2h(v3) << 16);
            }
        }
    }
}

// ------------------------- fused sampler + GEMM2 -------------------------
// C[m][n=256] = S[m][k=2304] @ w2t[n][k], S built on the fly from g_hh.
__global__ void __launch_bounds__(512, 1) tc_gemm2_f() {
    extern __shared__ char ds[];
    const int tid = threadIdx.x;
    const int lane = tid & 31;
    const int wid = tid >> 5;
    const int g = lane >> 2;
    const int tq = lane & 3;
    const int mw = wid & 3;
    const int nw = wid >> 2;
    const int m0 = blockIdx.x * 128;
    const int b_img = m0 >> 10;
    const int hw0 = m0 & 1023;
    const uns sb = smem_u32(ds);
    const us* hbase = g_hh + ((size_t)b_img << 18);

    // ---- setup: sampling table for 128 rows x 9 taps ----
    for (int it = tid; it < 1152; it += 512) {
        int row = it / 9;
        int k = it - row * 9;
        int hw = hw0 + row;
        int y = hw >> 5, x = hw & 31;
        float oy = g_off[((b_img * 18 + 2 * k) << 10) + hw];
        float ox = g_off[((b_img * 18 + 2 * k + 1) << 10) + hw];
        float py = (float)(y + k / 3 - 1) + oy;
        float px = (float)(x + k % 3 - 1) + ox;
        float y0f = floorf(py), x0f = floorf(px);
        float wy = py - y0f, wx = px - x0f;
        int y0 = (int)y0f, x0 = (int)x0f;
        int y1 = y0 + 1, x1 = x0 + 1;
        float vy0 = (y0 >= 0 && y0 <= 31) ? 1.0f : 0.0f;
        float vy1 = (y1 >= 0 && y1 <= 31) ? 1.0f : 0.0f;
        float vx0 = (x0 >= 0 && x0 <= 31) ? 1.0f : 0.0f;
        float vx1 = (x1 >= 0 && x1 <= 31) ? 1.0f : 0.0f;
        float4 w;
        w.x = (1.0f - wy) * (1.0f - wx) * vy0 * vx0;
        w.y = (1.0f - wy) * wx * vy0 * vx1;
        w.z = wy * (1.0f - wx) * vy1 * vx0;
        w.w = wy * wx * vy1 * vx1;
        int y0c = min(max(y0, 0), 31), y1c = min(max(y1, 0), 31);
        int x0c = min(max(x0, 0), 31), x1c = min(max(x1, 0), 31);
        *(float4*)(ds + P_W + it * 16) = w;
        *(ushort4*)(ds + P_I + it * 8) =
            make_ushort4((us)(y0c * 32 + x0c), (us)(y0c * 32 + x1c),
                         (us)(y1c * 32 + x0c), (us)(y1c * 32 + x1c));
    }

    const int arow = tid >> 2;     // A loader: 128 rows x 4 chunks
    const int ac = tid & 3;

    auto issueB = [&](int t) {
        const int k0 = t * KT;
        const uns st = sb + (t % NSTAGE) * STAGE;
#pragma unroll
        for (int r = 0; r < 2; r++) {
            int i = tid + 512 * r;
            int row = i >> 2, c = i & 3;
            cpa(st + OFF_B + row * 80 + c * 16, g_w2h + (size_t)row * 2304 + k0 + c * 8);
        }
        cpa_commit();
    };

    auto ldgA = [&](int t, float4& wv, uint4& q0, uint4& q1, uint4& q2, uint4& q3) {
        const int k0 = t * KT;
        const int tap = k0 >> 8;
        const int c0 = (k0 & 255) + ac * 8;
        int it = arow * 9 + tap;
        wv = *(const float4*)(ds + P_W + it * 16);
        ushort4 iv = *(const ushort4*)(ds + P_I + it * 8);
        q0 = *(const uint4*)(hbase + ((int)iv.x << 8) + c0);
        q1 = *(const uint4*)(hbase + ((int)iv.y << 8) + c0);
        q2 = *(const uint4*)(hbase + ((int)iv.z << 8) + c0);
        q3 = *(const uint4*)(hbase + ((int)iv.w << 8) + c0);
    };
    auto stsA = [&](int t, float4 wv, uint4 q0, uint4 q1, uint4 q2, uint4 q3) {
        const uns* a0 = (const uns*)&q0;
        const uns* a1 = (const uns*)&q1;
        const uns* a2 = (const uns*)&q2;
        const uns* a3 = (const uns*)&q3;
        uint4 o;
#pragma unroll
        for (int j = 0; j < 4; j++) {
            float2 f0 = __half22float2(*(const __half2*)&a0[j]);
            float2 f1 = __half22float2(*(const __half2*)&a1[j]);
            float2 f2 = __half22float2(*(const __half2*)&a2[j]);
            float2 f3 = __half22float2(*(const __half2*)&a3[j]);
            float lo = fmaf(wv.w, f3.x, fmaf(wv.z, f2.x, fmaf(wv.y, f1.x, wv.x * f0.x)));
            float hi = fmaf(wv.w, f3.y, fmaf(wv.z, f2.y, fmaf(wv.y, f1.y, wv.x * f0.y)));
            ((uns*)&o)[j] = pack2h(lo, hi);
        }
        *(uint4*)(ds + (t % NSTAGE) * STAGE + arow * 80 + ac * 16) = o;
    };

    float acc[2][8][4];
#pragma unroll
    for (int i = 0; i < 2; i++)
#pragma unroll
        for (int j = 0; j < 8; j++)
#pragma unroll
            for (int c = 0; c < 4; c++) acc[i][j][c] = 0.0f;

    const int aRow  = (lane & 7) + ((lane >> 3) & 1) * 8;
    const int aColB = (lane >> 4) * 16;

    issueB(0); issueB(1);
    __syncthreads();             // sampling table ready
    {
        float4 wv; uint4 q0, q1, q2, q3;
        ldgA(0, wv, q0, q1, q2, q3);
        stsA(0, wv, q0, q1, q2, q3);
    }

    const int T = 2304 / KT;     // 72
    for (int t = 0; t < T; t++) {
        cpa_wait<1>();
        __syncthreads();
        if (t + 2 < T) issueB(t + 2); else cpa_commit();
        float4 wv; uint4 q0, q1, q2, q3;
        const bool have = (t + 1 < T);
        if (have) ldgA(t + 1, wv, q0, q1, q2, q3);
        const uns st = sb + (t % NSTAGE) * STAGE;
#pragma unroll
        for (int kk = 0; kk < 2; kk++) {
            uns ah[2][4], bh[8][2];
#pragma unroll
            for (int mt = 0; mt < 2; mt++) {
                uns addr = st + (mw * 32 + mt * 16 + aRow) * 80 + kk * 32 + aColB;
                ldsm4(ah[mt], addr);
            }
#pragma unroll
            for (int p = 0; p < 4; p++) {
                uns r4[4];
                uns addr = st + OFF_B + (nw * 64 + p * 16 + aRow) * 80 + kk * 32 + aColB;
                ldsm4(r4, addr);
                bh[2 * p][0] = r4[0]; bh[2 * p + 1][0] = r4[1];
                bh[2 * p][1] = r4[2]; bh[2 * p + 1][1] = r4[3];
            }
#pragma unroll
            for (int mt = 0; mt < 2; mt++)
#pragma unroll
                for (int nt = 0; nt < 8; nt++)
                    mma_f16(acc[mt][nt], ah[mt], bh[nt]);
        }
        if (have) stsA(t + 1, wv, q0, q1, q2, q3);
    }

    // epilogue -> g_h2h (+bn2+relu)
    us* dh = g_h2h + (size_t)m0 * 256;
#pragma unroll
    for (int mt = 0; mt < 2; mt++) {
#pragma unroll
        for (int nt = 0; nt < 8; nt++) {
            int row = mw * 32 + mt * 16 + g;
            int col = nw * 64 + nt * 8 + 2 * tq;
            float s0 = g_s2[col], t0 = g_t2[col];
            float s1 = g_s2[col + 1], t1 = g_t2[col + 1];
            float v0 = fmaxf(fmaf(acc[mt][nt][0], s0, t0), 0.0f);
            float v1 = fmaxf(fmaf(acc[mt][nt][1], s1, t1), 0.0f);
            float v2 = fmaxf(fmaf(acc[mt][nt][2], s0, t0), 0.0f);
            float v3 = fmaxf(fmaf(acc[mt][nt][3], s1, t1), 0.0f);
            *(uns*)(dh + (size_t)row * 256 + col) = (uns)f2h(v0) | ((uns)f2h(v1) << 16);
            *(uns*)(dh + (size_t)(row + 8) * 256 + col) = (uns)f2h(v2) | ((uns)f2h(v3) << 16);
        }
    }
}

// ------------------------- offset conv as GEMM -------------------------
__global__ void __launch_bounds__(128, 4) off_gemm(const float* __restrict__ off_b) {
    extern __shared__ char ds[];
    const int tid = threadIdx.x;
    const int lane = tid & 31;
    const int wid = tid >> 5;
    const int g = lane >> 2;
    const int tq = lane & 3;
    const int m0 = blockIdx.x * 64;
    const int b_img = m0 >> 10;
    const int hw0 = m0 & 1023;
    const uns sb = smem_u32(ds);

    auto issue = [&](int t) {
        const int k0 = t * KT;
        const int tap = k0 >> 8;
        const int c0 = k0 & 255;
        const int dy = tap / 3 - 1, dx = tap % 3 - 1;
        const uns st = sb + (t & 3) * OSTAGE;
        {
            int row = tid >> 2, c = tid & 3;
            const us* src = g_offwT + row * 2304 + k0 + c * 8;
            cpa(st + OFF_OB + row * 80 + c * 16, src);
        }
#pragma unroll
        for (int r = 0; r < 2; r++) {
            int i = tid + 128 * r;
            int row = i >> 2, c = i & 3;
            int hw = hw0 + row;
            int y = hw >> 5, x = hw & 31;
            int yy = y + dy, xx = x + dx;
            uns ok = (yy >= 0 && yy < 32 && xx >= 0 && xx < 32) ? 16u : 0u;
            int yc = min(max(yy, 0), 31), xc = min(max(xx, 0), 31);
            const us* src = g_hh + ((size_t)((b_img << 10) + (yc << 5) + xc)) * 256 + c0 + c * 8;
            cpa_z(st + row * 80 + c * 16, src, ok);
        }
        cpa_commit();
    };

    float acc[4][4];
#pragma unroll
    for (int j = 0; j < 4; j++)
#pragma unroll
        for (int c = 0; c < 4; c++) acc[j][c] = 0.0f;

    const int aRow  = (lane & 7) + ((lane >> 3) & 1) * 8;
    const int aColB = (lane >> 4) * 16;

    issue(0); issue(1); issue(2);

    const int T = 2304 / KT;   // 72
    for (int t = 0; t < T; t++) {
        cpa_wait<2>();
        __syncthreads();
        if (t + 3 < T) issue(t + 3); else cpa_commit();
        const uns st = sb + (t & 3) * OSTAGE;
#pragma unroll
        for (int kk = 0; kk < 2; kk++) {
            uns ah[4], bh[4][2];
            {
                uns addr = st + (wid * 16 + aRow) * 80 + kk * 32 + aColB;
                ldsm4(ah, addr);
            }
#pragma unroll
            for (int p = 0; p < 2; p++) {
                uns r4[4];
                uns addr = st + OFF_OB + (p * 16 + aRow) * 80 + kk * 32 + aColB;
                ldsm4(r4, addr);
                bh[2 * p][0] = r4[0]; bh[2 * p + 1][0] = r4[1];
                bh[2 * p][1] = r4[2]; bh[2 * p + 1][1] = r4[3];
            }
#pragma unroll
            for (int nt = 0; nt < 4; nt++)
                mma_f16(acc[nt], ah, bh[nt]);
        }
        __syncthreads();
    }

    float* dst = g_off + (size_t)b_img * (18 * HW) + hw0;
#pragma unroll
    for (int nt = 0; nt < 4; nt++) {
        int col = nt * 8 + 2 * tq;
        int row = wid * 16 + g;
        if (col < 18) {
            float bb = off_b[col];
            dst[col * HW + row] = acc[nt][0] + bb;
            dst[col * HW + row + 8] = acc[nt][2] + bb;
        }
        if (col + 1 < 18) {
            float bb = off_b[col + 1];
            dst[(col + 1) * HW + row] = acc[nt][1] + bb;
            dst[(col + 1) * HW + row + 8] = acc[nt][3] + bb;
        }
    }
}

// ------------------------- launcher -------------------------
extern "C" void kernel_launch(void* const* d_in, const int* in_sizes, int n_in,
                              void* d_out, int out_size) {
    const float* x     = (const float*)d_in[0];
    const float* w1    = (const float*)d_in[1];
    const float* bn1g  = (const float*)d_in[2];
    const float* bn1b  = (const float*)d_in[3];
    const float* bn1m  = (const float*)d_in[4];
    const float* bn1v  = (const float*)d_in[5];
    const float* off_w = (const float*)d_in[6];
    const float* off_b = (const float*)d_in[7];
    const float* w2    = (const float*)d_in[8];
    const float* bn2g  = (const float*)d_in[9];
    const float* bn2b  = (const float*)d_in[10];
    const float* bn2m  = (const float*)d_in[11];
    const float* bn2v  = (const float*)d_in[12];
    const float* w3    = (const float*)d_in[13];
    const float* bn3g  = (const float*)d_in[14];
    const float* bn3b  = (const float*)d_in[15];
    const float* bn3m  = (const float*)d_in[16];
    const float* bn3v  = (const float*)d_in[17];
    float* out = (float*)d_out;

    cudaFuncSetAttribute(tc_gemm<1>, cudaFuncAttributeMaxDynamicSharedMemorySize, SMEM_TOTAL);
    cudaFuncSetAttribute(tc_gemm<3>, cudaFuncAttributeMaxDynamicSharedMemorySize, SMEM_TOTAL);
    cudaFuncSetAttribute(tc_gemm2_f, cudaFuncAttributeMaxDynamicSharedMemorySize, SMEM2_TOTAL);
    cudaFuncSetAttribute(off_gemm, cudaFuncAttributeMaxDynamicSharedMemorySize, OSMEM_TOTAL);

    prep_kernel<<<3108, 256>>>(off_w, w2, w1, w3,
                               bn1g, bn1b, bn1m, bn1v,
                               bn2g, bn2b, bn2m, bn2v,
                               bn3g, bn3b, bn3m, bn3v);
    tc_gemm<1><<<128, 512, SMEM_TOTAL>>>(x, nullptr);
    off_gemm<<<256, 128, OSMEM_TOTAL>>>(off_b);
    tc_gemm2_f<<<128, 512, SMEM2_TOTAL>>>();      // 4th launch: ncu slot
    tc_gemm<3><<<dim3(128, 4), 512, SMEM_TOTAL>>>(x, out);
}

// round 16
// speedup vs baseline: 1.0897x; 1.0240x over previous
#include <cuda_runtime.h>
#include <cuda_fp16.h>

// ---------------------------------------------------------------------------
// DeformableBottleneck: B=16, Cin=O=1024, H=W=32, P=256.
// All convs as fp16 mma.sync GEMMs, fp32 accumulate.
// GEMM2 fuses bilinear sampling into its A-loader (hfma2 combine),
// 64-row m-tiles, 256 thr, 2 CTAs/SM, grid 256.
// ---------------------------------------------------------------------------

#define HW 1024
#define CIN 1024
#define PDIM 256
#define ODIM 1024
#define BATCH 16
#define KT 32

typedef unsigned uns;
typedef unsigned short us;

__device__ us    g_hh [BATCH * HW * PDIM];          // h1 fp16, NHWC
__device__ us    g_h2h[BATCH * HW * PDIM];          // h2 fp16
__device__ float g_off[BATCH * 18 * HW];
__device__ us    g_w1h[PDIM * CIN];
__device__ us    g_w2h[PDIM * 9 * PDIM];
__device__ us    g_w3h[ODIM * PDIM];
__device__ us    g_offwT[32 * 9 * PDIM];            // [j(pad32)][tap*256+c]
__device__ float g_s1[PDIM], g_t1[PDIM];
__device__ float g_s2[PDIM], g_t2[PDIM];
__device__ float g_s3[ODIM], g_t3[ODIM];

// main GEMM smem stage: A 0 (10240), B 10240 (20480)
#define OFF_B  10240
#define STAGE  30720
#define NSTAGE 3
#define SMEM_TOTAL (NSTAGE * STAGE)     // 92160 B

// fused GEMM2 (64-row tiles): A 0 (5120), B 5120 (20480); stage 25600
#define OFF_B2 5120
#define G2STG  25600
#define P_W    (3 * G2STG)              // 76800: 576 * uint4 (dup-half2 weights)
#define P_I    (P_W + 9216)             // 86016: 576 * ushort4 (corner indices)
#define SMEM2_TOTAL (P_I + 4608)        // 90624 B -> 2 CTAs/SM

// off_gemm smem stage: A 0 (5120), B 5120 (2560)
#define OFF_OB  5120
#define OSTAGE  7680
#define OSMEM_TOTAL (4 * OSTAGE)        // 30720 B

// ------------------------- PTX helpers -------------------------
__device__ __forceinline__ uns smem_u32(const void* p) {
    uns r;
    asm("{ .reg .u64 t; cvta.to.shared.u64 t, %1; cvt.u32.u64 %0, t; }"
        : "=r"(r) : "l"(p));
    return r;
}
__device__ __forceinline__ void cpa(uns dst, const void* src) {
    asm volatile("cp.async.cg.shared.global [%0], [%1], 16;" :: "r"(dst), "l"(src) : "memory");
}
__device__ __forceinline__ void cpa_z(uns dst, const void* src, uns sz) {
    asm volatile("cp.async.cg.shared.global [%0], [%1], 16, %2;"
                 :: "r"(dst), "l"(src), "r"(sz) : "memory");
}
__device__ __forceinline__ void cpa_commit() {
    asm volatile("cp.async.commit_group;" ::: "memory");
}
template <int N> __device__ __forceinline__ void cpa_wait() {
    asm volatile("cp.async.wait_group %0;" :: "n"(N) : "memory");
}
__device__ __forceinline__ void ldsm4(uns* r, uns a) {
    asm volatile("ldmatrix.sync.aligned.m8n8.x4.shared.b16 {%0,%1,%2,%3}, [%4];"
                 : "=r"(r[0]), "=r"(r[1]), "=r"(r[2]), "=r"(r[3]) : "r"(a));
}
__device__ __forceinline__ void ldsm4t(uns* r, uns a) {
    asm volatile("ldmatrix.sync.aligned.m8n8.x4.trans.shared.b16 {%0,%1,%2,%3}, [%4];"
                 : "=r"(r[0]), "=r"(r[1]), "=r"(r[2]), "=r"(r[3]) : "r"(a));
}
__device__ __forceinline__ void mma_f16(float* d, const uns* a, const uns* b) {
    asm volatile(
        "mma.sync.aligned.m16n8k16.row.col.f32.f16.f16.f32 "
        "{%0,%1,%2,%3}, {%4,%5,%6,%7}, {%8,%9}, {%0,%1,%2,%3};"
        : "+f"(d[0]), "+f"(d[1]), "+f"(d[2]), "+f"(d[3])
        : "r"(a[0]), "r"(a[1]), "r"(a[2]), "r"(a[3]), "r"(b[0]), "r"(b[1]));
}
__device__ __forceinline__ us f2h(float x) {
    return __half_as_ushort(__float2half_rn(x));
}
__device__ __forceinline__ uns pack2h(float a, float b) {
    __half2 h = __floats2half2_rn(a, b);
    return *(uns*)&h;
}
__device__ __forceinline__ __half2 u2h2(uns u) { return *(__half2*)&u; }

// ------------------------- merged prep kernel -------------------------
__global__ void prep_kernel(const float* __restrict__ off_w,
                            const float* __restrict__ w2,
                            const float* __restrict__ w1,
                            const float* __restrict__ w3,
                            const float* __restrict__ g1, const float* __restrict__ b1,
                            const float* __restrict__ m1, const float* __restrict__ v1,
                            const float* __restrict__ g2, const float* __restrict__ b2,
                            const float* __restrict__ m2, const float* __restrict__ v2,
                            const float* __restrict__ g3, const float* __restrict__ b3,
                            const float* __restrict__ m3, const float* __restrict__ v3) {
    int blk = blockIdx.x;
    int tid = threadIdx.x;
    if (blk < 288) {
        int idx = blk * 256 + tid;                  // < 32*2304
        int j = idx / 2304;
        int r = idx % 2304;
        int tap = r >> 8;
        int c = r & 255;
        g_offwT[idx] = (j < 18) ? f2h(off_w[(j * 256 + c) * 9 + tap]) : (us)0;
    } else if (blk < 2592) {
        int idx = (blk - 288) * 256 + tid;          // < 256*2304
        int o = idx / 2304;
        int r = idx % 2304;
        int k = r >> 8;
        int c = r & 255;
        g_w2h[idx] = f2h(w2[(o * 256 + c) * 9 + k]);
    } else if (blk < 2848) {
        int i = (blk - 2592) * 256 + tid;           // < 65536 float4s
        float4 v = ((const float4*)w1)[i];
        ((ushort4*)g_w1h)[i] = make_ushort4(f2h(v.x), f2h(v.y), f2h(v.z), f2h(v.w));
    } else if (blk < 3104) {
        int i = (blk - 2848) * 256 + tid;
        float4 v = ((const float4*)w3)[i];
        ((ushort4*)g_w3h)[i] = make_ushort4(f2h(v.x), f2h(v.y), f2h(v.z), f2h(v.w));
    } else {
        int i = (blk - 3104) * 256 + tid;
        if (i < PDIM) {
            float s = g1[i] / sqrtf(v1[i] + 1e-5f);
            g_s1[i] = s; g_t1[i] = b1[i] - m1[i] * s;
            s = g2[i] / sqrtf(v2[i] + 1e-5f);
            g_s2[i] = s; g_t2[i] = b2[i] - m2[i] * s;
        }
        if (i < ODIM) {
            float s = g3[i] / sqrtf(v3[i] + 1e-5f);
            g_s3[i] = s; g_t3[i] = b3[i] - m3[i] * s;
        }
    }
}

// ------------------------- main tensor-core GEMM (modes 1, 3) ----------------
template <int MODE>
__global__ void __launch_bounds__(512, 1) tc_gemm(const float* __restrict__ Xres,
                                                  float* __restrict__ Out) {
    extern __shared__ char ds[];
    constexpr int Ktot = (MODE == 1) ? 1024 : 256;
    constexpr int T = Ktot / KT;

    const int tid = threadIdx.x;
    const int lane = tid & 31;
    const int wid = tid >> 5;
    const int g = lane >> 2;
    const int tq = lane & 3;
    const int mw = wid & 3;
    const int nw = wid >> 2;
    const int n0 = (MODE == 3) ? blockIdx.y * 256 : 0;

    const us *Ah_g = nullptr, *Bh_g;
    const float* Xf = nullptr;
    int m0 = 0, b_img = 0, hw0 = 0;
    if constexpr (MODE == 1) {
        b_img = blockIdx.x >> 3;
        hw0 = (blockIdx.x & 7) << 7;
        Xf = Xres + (size_t)b_img * (CIN * HW);
        Bh_g = g_w1h;
    } else {
        m0 = blockIdx.x * 128;
        Ah_g = g_h2h;
        Bh_g = g_w3h + (size_t)n0 * Ktot;
    }

    const uns sb = smem_u32(ds);

    auto issueB = [&](int t) {
        const int k0 = t * KT;
        const uns st = sb + (t % NSTAGE) * STAGE;
#pragma unroll
        for (int r = 0; r < 2; r++) {
            int i = tid + 512 * r;
            int row = i >> 2, c = i & 3;
            const us* sh = Bh_g + (size_t)row * Ktot + k0 + c * 8;
            cpa(st + OFF_B + row * 80 + c * 16, sh);
        }
        if constexpr (MODE != 1) {
            int row = tid >> 2, c = tid & 3;
            const us* sh = Ah_g + (size_t)(m0 + row) * Ktot + k0 + c * 8;
            cpa(st + row * 80 + c * 16, sh);
        }
        cpa_commit();
    };
    auto buildA = [&](int t) {
        if constexpr (MODE == 1) {
            const int k0 = t * KT;
            const uns st = sb + (t % NSTAGE) * STAGE;
            int row = tid >> 4, c = tid & 15;
            const float* src = Xf + (size_t)(k0 + row) * HW + hw0 + c * 8;
            float4 a = *(const float4*)(src);
            float4 b = *(const float4*)(src + 4);
            uint4 o;
            o.x = pack2h(a.x, a.y);
            o.y = pack2h(a.z, a.w);
            o.z = pack2h(b.x, b.y);
            o.w = pack2h(b.z, b.w);
            *(uint4*)(ds + (st - sb) + row * 272 + c * 16) = o;
        }
    };

    float acc[2][8][4];
#pragma unroll
    for (int i = 0; i < 2; i++)
#pragma unroll
        for (int j = 0; j < 8; j++)
#pragma unroll
            for (int c = 0; c < 4; c++) acc[i][j][c] = 0.0f;

    const int aRow  = (lane & 7) + ((lane >> 3) & 1) * 8;
    const int aColB = (lane >> 4) * 16;
    const int tRow  = (lane & 7) + ((lane >> 4) & 1) * 8;
    const int tColB = ((lane >> 3) & 1) * 16;

    issueB(0); issueB(1);
    buildA(0); buildA(1);

    for (int t = 0; t < T; t++) {
        cpa_wait<1>();
        __syncthreads();
        if (t + 2 < T) { issueB(t + 2); buildA(t + 2); }
        else cpa_commit();
        const uns st = sb + (t % NSTAGE) * STAGE;
#pragma unroll
        for (int kk = 0; kk < 2; kk++) {
            uns ah[2][4], bh[8][2];
#pragma unroll
            for (int mt = 0; mt < 2; mt++) {
                if constexpr (MODE == 1) {
                    uns addr = st + (kk * 16 + tRow) * 272 + (mw * 32 + mt * 16) * 2 + tColB;
                    ldsm4t(ah[mt], addr);
                } else {
                    uns addr = st + (mw * 32 + mt * 16 + aRow) * 80 + kk * 32 + aColB;
                    ldsm4(ah[mt], addr);
                }
            }
#pragma unroll
            for (int p = 0; p < 4; p++) {
                uns r4[4];
                uns addr = st + OFF_B + (nw * 64 + p * 16 + aRow) * 80 + kk * 32 + aColB;
                ldsm4(r4, addr);
                bh[2 * p][0] = r4[0]; bh[2 * p + 1][0] = r4[1];
                bh[2 * p][1] = r4[2]; bh[2 * p + 1][1] = r4[3];
            }
#pragma unroll
            for (int mt = 0; mt < 2; mt++)
#pragma unroll
                for (int nt = 0; nt < 8; nt++)
                    mma_f16(acc[mt][nt], ah[mt], bh[nt]);
        }
    }

    // ---------------- epilogue ----------------
    if constexpr (MODE == 3) {
        float* Cs = (float*)ds;   // [128 n][132]
        int bb = m0 >> 10;
        int hwb = m0 & 1023;
        size_t obase = ((size_t)bb << 20) + hwb;
#pragma unroll
        for (int half = 0; half < 2; half++) {
            __syncthreads();
            if ((nw >> 1) == half) {
                int colbase = (nw & 1) * 64;
#pragma unroll
                for (int mt = 0; mt < 2; mt++) {
#pragma unroll
                    for (int nt = 0; nt < 8; nt++) {
                        int row = mw * 32 + mt * 16 + g;
                        int col = colbase + nt * 8 + 2 * tq;
                        Cs[(col)     * 132 + row]     = acc[mt][nt][0];
                        Cs[(col + 1) * 132 + row]     = acc[mt][nt][1];
                        Cs[(col)     * 132 + row + 8] = acc[mt][nt][2];
                        Cs[(col + 1) * 132 + row + 8] = acc[mt][nt][3];
                    }
                }
            }
            __syncthreads();
#pragma unroll
            for (int i = 0; i < 32; i++) {
                int idx = i * 512 + tid;
                int nl = idx >> 7;
                int ml = idx & 127;
                int n = n0 + half * 128 + nl;
                float v = fmaf(Cs[nl * 132 + ml], g_s3[n], g_t3[n]);
                size_t addr = obase + ((size_t)n << 10) + ml;
                v += Xres[addr];
                Out[addr] = fmaxf(v, 0.0f);
            }
        }
    } else {
        us* dh = g_hh + ((size_t)((b_img << 10) + hw0)) * 256;
#pragma unroll
        for (int mt = 0; mt < 2; mt++) {
#pragma unroll
            for (int nt = 0; nt < 8; nt++) {
                int row = mw * 32 + mt * 16 + g;
                int col = nw * 64 + nt * 8 + 2 * tq;
                float s0 = g_s1[col], t0 = g_t1[col];
                float s1 = g_s1[col + 1], t1 = g_t1[col + 1];
                float v0 = fmaxf(fmaf(acc[mt][nt][0], s0, t0), 0.0f);
                float v1 = fmaxf(fmaf(acc[mt][nt][1], s1, t1), 0.0f);
                float v2 = fmaxf(fmaf(acc[mt][nt][2], s0, t0), 0.0f);
                float v3 = fmaxf(fmaf(acc[mt][nt][3], s1, t1), 0.0f);
                *(uns*)(dh + (size_t)row * 256 + col) = (uns)f2h(v0) | ((uns)f2h(v1) << 16);
                *(uns*)(dh + (size_t)(row + 8) * 256 + col) = (uns)f2h(v2) | ((uns)f2h(v3) << 16);
            }
        }
    }
}

// ------------------------- fused sampler + GEMM2 -------------------------
// C[m][n=256] = S[m][k=2304] @ w2t[n][k]; 64-row m-tiles, grid 256,
// 256 threads (8 warps: 2m x 4n, warp tile 32x64), 2 CTAs/SM.
__global__ void __launch_bounds__(256, 2) tc_gemm2_f() {
    extern __shared__ char ds[];
    const int tid = threadIdx.x;
    const int lane = tid & 31;
    const int wid = tid >> 5;
    const int g = lane >> 2;
    const int tq = lane & 3;
    const int mw = wid & 1;          // 2 m groups of 32 rows
    const int nw = wid >> 1;         // 4 n groups of 64 cols
    const int m0 = blockIdx.x * 64;
    const int b_img = m0 >> 10;
    const int hw0 = m0 & 1023;
    const uns sb = smem_u32(ds);
    const us* hbase = g_hh + ((size_t)b_img << 18);

    // ---- setup: sampling table for 64 rows x 9 taps ----
    for (int it = tid; it < 576; it += 256) {
        int row = it / 9;
        int k = it - row * 9;
        int hw = hw0 + row;
        int y = hw >> 5, x = hw & 31;
        float oy = g_off[((b_img * 18 + 2 * k) << 10) + hw];
        float ox = g_off[((b_img * 18 + 2 * k + 1) << 10) + hw];
        float py = (float)(y + k / 3 - 1) + oy;
        float px = (float)(x + k % 3 - 1) + ox;
        float y0f = floorf(py), x0f = floorf(px);
        float wy = py - y0f, wx = px - x0f;
        int y0 = (int)y0f, x0 = (int)x0f;
        int y1 = y0 + 1, x1 = x0 + 1;
        float vy0 = (y0 >= 0 && y0 <= 31) ? 1.0f : 0.0f;
        float vy1 = (y1 >= 0 && y1 <= 31) ? 1.0f : 0.0f;
        float vx0 = (x0 >= 0 && x0 <= 31) ? 1.0f : 0.0f;
        float vx1 = (x1 >= 0 && x1 <= 31) ? 1.0f : 0.0f;
        float w00 = (1.0f - wy) * (1.0f - wx) * vy0 * vx0;
        float w01 = (1.0f - wy) * wx * vy0 * vx1;
        float w10 = wy * (1.0f - wx) * vy1 * vx0;
        float w11 = wy * wx * vy1 * vx1;
        int y0c = min(max(y0, 0), 31), y1c = min(max(y1, 0), 31);
        int x0c = min(max(x0, 0), 31), x1c = min(max(x1, 0), 31);
        *(uint4*)(ds + P_W + it * 16) =
            make_uint4(pack2h(w00, w00), pack2h(w01, w01),
                       pack2h(w10, w10), pack2h(w11, w11));
        *(ushort4*)(ds + P_I + it * 8) =
            make_ushort4((us)(y0c * 32 + x0c), (us)(y0c * 32 + x1c),
                         (us)(y1c * 32 + x0c), (us)(y1c * 32 + x1c));
    }

    const int arow = tid >> 2;     // A loader: 64 rows x 4 chunks
    const int ac = tid & 3;

    auto issueB = [&](int t) {
        const int k0 = t * KT;
        const uns st = sb + (t % 3) * G2STG;
#pragma unroll
        for (int r = 0; r < 4; r++) {
            int i = tid + 256 * r;
            int row = i >> 2, c = i & 3;
            cpa(st + OFF_B2 + row * 80 + c * 16, g_w2h + (size_t)row * 2304 + k0 + c * 8);
        }
        cpa_commit();
    };

    auto ldgA = [&](int t, uint4& wq, uint4& q0, uint4& q1, uint4& q2, uint4& q3) {
        const int k0 = t * KT;
        const int tap = k0 >> 8;
        const int c0 = (k0 & 255) + ac * 8;
        int it = arow * 9 + tap;
        wq = *(const uint4*)(ds + P_W + it * 16);
        ushort4 iv = *(const ushort4*)(ds + P_I + it * 8);
        q0 = *(const uint4*)(hbase + ((int)iv.x << 8) + c0);
        q1 = *(const uint4*)(hbase + ((int)iv.y << 8) + c0);
        q2 = *(const uint4*)(hbase + ((int)iv.z << 8) + c0);
        q3 = *(const uint4*)(hbase + ((int)iv.w << 8) + c0);
    };
    auto stsA = [&](int t, uint4 wq, uint4 q0, uint4 q1, uint4 q2, uint4 q3) {
        const uns* a0 = (const uns*)&q0;
        const uns* a1 = (const uns*)&q1;
        const uns* a2 = (const uns*)&q2;
        const uns* a3 = (const uns*)&q3;
        uint4 o;
#pragma unroll
        for (int j = 0; j < 4; j++) {
            __half2 v = __hmul2(u2h2(a0[j]), u2h2(wq.x));
            v = __hfma2(u2h2(a1[j]), u2h2(wq.y), v);
            v = __hfma2(u2h2(a2[j]), u2h2(wq.z), v);
            v = __hfma2(u2h2(a3[j]), u2h2(wq.w), v);
            ((uns*)&o)[j] = *(uns*)&v;
        }
        *(uint4*)(ds + (t % 3) * G2STG + arow * 80 + ac * 16) = o;
    };

    float acc[2][8][4];
#pragma unroll
    for (int i = 0; i < 2; i++)
#pragma unroll
        for (int j = 0; j < 8; j++)
#pragma unroll
            for (int c = 0; c < 4; c++) acc[i][j][c] = 0.0f;

    const int aRow  = (lane & 7) + ((lane >> 3) & 1) * 8;
    const int aColB = (lane >> 4) * 16;

    issueB(0); issueB(1);
    __syncthreads();             // sampling table ready
    {
        uint4 wq, q0, q1, q2, q3;
        ldgA(0, wq, q0, q1, q2, q3);
        stsA(0, wq, q0, q1, q2, q3);
    }

    const int T = 2304 / KT;     // 72
    for (int t = 0; t < T; t++) {
        cpa_wait<1>();
        __syncthreads();
        if (t + 2 < T) issueB(t + 2); else cpa_commit();
        uint4 wq, q0, q1, q2, q3;
        const bool have = (t + 1 < T);
        if (have) ldgA(t + 1, wq, q0, q1, q2, q3);
        const uns st = sb + (t % 3) * G2STG;
#pragma unroll
        for (int kk = 0; kk < 2; kk++) {
            uns ah[2][4], bh[8][2];
#pragma unroll
            for (int mt = 0; mt < 2; mt++) {
                uns addr = st + (mw * 32 + mt * 16 + aRow) * 80 + kk * 32 + aColB;
                ldsm4(ah[mt], addr);
            }
#pragma unroll
            for (int p = 0; p < 4; p++) {
                uns r4[4];
                uns addr = st + OFF_B2 + (nw * 64 + p * 16 + aRow) * 80 + kk * 32 + aColB;
                ldsm4(r4, addr);
                bh[2 * p][0] = r4[0]; bh[2 * p + 1][0] = r4[1];
                bh[2 * p][1] = r4[2]; bh[2 * p + 1][1] = r4[3];
            }
#pragma unroll
            for (int mt = 0; mt < 2; mt++)
#pragma unroll
                for (int nt = 0; nt < 8; nt++)
                    mma_f16(acc[mt][nt], ah[mt], bh[nt]);
        }
        if (have) stsA(t + 1, wq, q0, q1, q2, q3);
    }

    // epilogue -> g_h2h (+bn2+relu)
    us* dh = g_h2h + (size_t)m0 * 256;
#pragma unroll
    for (int mt = 0; mt < 2; mt++) {
#pragma unroll
        for (int nt = 0; nt < 8; nt++) {
            int row = mw * 32 + mt * 16 + g;
            int col = nw * 64 + nt * 8 + 2 * tq;
            float s0 = g_s2[col], t0 = g_t2[col];
            float s1 = g_s2[col + 1], t1 = g_t2[col + 1];
            float v0 = fmaxf(fmaf(acc[mt][nt][0], s0, t0), 0.0f);
            float v1 = fmaxf(fmaf(acc[mt][nt][1], s1, t1), 0.0f);
            float v2 = fmaxf(fmaf(acc[mt][nt][2], s0, t0), 0.0f);
            float v3 = fmaxf(fmaf(acc[mt][nt][3], s1, t1), 0.0f);
            *(uns*)(dh + (size_t)row * 256 + col) = (uns)f2h(v0) | ((uns)f2h(v1) << 16);
            *(uns*)(dh + (size_t)(row + 8) * 256 + col) = (uns)f2h(v2) | ((uns)f2h(v3) << 16);
        }
    }
}

// ------------------------- offset conv as GEMM -------------------------
__global__ void __launch_bounds__(128, 4) off_gemm(const float* __restrict__ off_b) {
    extern __shared__ char ds[];
    const int tid = threadIdx.x;
    const int lane = tid & 31;
    const int wid = tid >> 5;
    const int g = lane >> 2;
    const int tq = lane & 3;
    const int m0 = blockIdx.x * 64;
    const int b_img = m0 >> 10;
    const int hw0 = m0 & 1023;
    const uns sb = smem_u32(ds);

    auto issue = [&](int t) {
        const int k0 = t * KT;
        const int tap = k0 >> 8;
        const int c0 = k0 & 255;
        const int dy = tap / 3 - 1, dx = tap % 3 - 1;
        const uns st = sb + (t & 3) * OSTAGE;
        {
            int row = tid >> 2, c = tid & 3;
            const us* src = g_offwT + row * 2304 + k0 + c * 8;
            cpa(st + OFF_OB + row * 80 + c * 16, src);
        }
#pragma unroll
        for (int r = 0; r < 2; r++) {
            int i = tid + 128 * r;
            int row = i >> 2, c = i & 3;
            int hw = hw0 + row;
            int y = hw >> 5, x = hw & 31;
            int yy = y + dy, xx = x + dx;
            uns ok = (yy >= 0 && yy < 32 && xx >= 0 && xx < 32) ? 16u : 0u;
            int yc = min(max(yy, 0), 31), xc = min(max(xx, 0), 31);
            const us* src = g_hh + ((size_t)((b_img << 10) + (yc << 5) + xc)) * 256 + c0 + c * 8;
            cpa_z(st + row * 80 + c * 16, src, ok);
        }
        cpa_commit();
    };

    float acc[4][4];
#pragma unroll
    for (int j = 0; j < 4; j++)
#pragma unroll
        for (int c = 0; c < 4; c++) acc[j][c] = 0.0f;

    const int aRow  = (lane & 7) + ((lane >> 3) & 1) * 8;
    const int aColB = (lane >> 4) * 16;

    issue(0); issue(1); issue(2);

    const int T = 2304 / KT;   // 72
    for (int t = 0; t < T; t++) {
        cpa_wait<2>();
        __syncthreads();
        if (t + 3 < T) issue(t + 3); else cpa_commit();
        const uns st = sb + (t & 3) * OSTAGE;
#pragma unroll
        for (int kk = 0; kk < 2; kk++) {
            uns ah[4], bh[4][2];
            {
                uns addr = st + (wid * 16 + aRow) * 80 + kk * 32 + aColB;
                ldsm4(ah, addr);
            }
#pragma unroll
            for (int p = 0; p < 2; p++) {
                uns r4[4];
                uns addr = st + OFF_OB + (p * 16 + aRow) * 80 + kk * 32 + aColB;
                ldsm4(r4, addr);
                bh[2 * p][0] = r4[0]; bh[2 * p + 1][0] = r4[1];
                bh[2 * p][1] = r4[2]; bh[2 * p + 1][1] = r4[3];
            }
#pragma unroll
            for (int nt = 0; nt < 4; nt++)
                mma_f16(acc[nt], ah, bh[nt]);
        }
        __syncthreads();
    }

    float* dst = g_off + (size_t)b_img * (18 * HW) + hw0;
#pragma unroll
    for (int nt = 0; nt < 4; nt++) {
        int col = nt * 8 + 2 * tq;
        int row = wid * 16 + g;
        if (col < 18) {
            float bb = off_b[col];
            dst[col * HW + row] = acc[nt][0] + bb;
            dst[col * HW + row + 8] = acc[nt][2] + bb;
        }
        if (col + 1 < 18) {
            float bb = off_b[col + 1];
            dst[(col + 1) * HW + row] = acc[nt][1] + bb;
            dst[(col + 1) * HW + row + 8] = acc[nt][3] + bb;
        }
    }
}

// ------------------------- launcher -------------------------
extern "C" void kernel_launch(void* const* d_in, const int* in_sizes, int n_in,
                              void* d_out, int out_size) {
    const float* x     = (const float*)d_in[0];
    const float* w1    = (const float*)d_in[1];
    const float* bn1g  = (const float*)d_in[2];
    const float* bn1b  = (const float*)d_in[3];
    const float* bn1m  = (const float*)d_in[4];
    const float* bn1v  = (const float*)d_in[5];
    const float* off_w = (const float*)d_in[6];
    const float* off_b = (const float*)d_in[7];
    const float* w2    = (const float*)d_in[8];
    const float* bn2g  = (const float*)d_in[9];
    const float* bn2b  = (const float*)d_in[10];
    const float* bn2m  = (const float*)d_in[11];
    const float* bn2v  = (const float*)d_in[12];
    const float* w3    = (const float*)d_in[13];
    const float* bn3g  = (const float*)d_in[14];
    const float* bn3b  = (const float*)d_in[15];
    const float* bn3m  = (const float*)d_in[16];
    const float* bn3v  = (const float*)d_in[17];
    float* out = (float*)d_out;

    cudaFuncSetAttribute(tc_gemm<1>, cudaFuncAttributeMaxDynamicSharedMemorySize, SMEM_TOTAL);
    cudaFuncSetAttribute(tc_gemm<3>, cudaFuncAttributeMaxDynamicSharedMemorySize, SMEM_TOTAL);
    cudaFuncSetAttribute(tc_gemm2_f, cudaFuncAttributeMaxDynamicSharedMemorySize, SMEM2_TOTAL);
    cudaFuncSetAttribute(off_gemm, cudaFuncAttributeMaxDynamicSharedMemorySize, OSMEM_TOTAL);

    prep_kernel<<<3108, 256>>>(off_w, w2, w1, w3,
                               bn1g, bn1b, bn1m, bn1v,
                               bn2g, bn2b, bn2m, bn2v,
                               bn3g, bn3b, bn3m, bn3v);
    tc_gemm<1><<<128, 512, SMEM_TOTAL>>>(x, nullptr);
    off_gemm<<<256, 128, OSMEM_TOTAL>>>(off_b);
    tc_gemm2_f<<<256, 256, SMEM2_TOTAL>>>();      // 4th launch: ncu slot
    tc_gemm<3><<<dim3(128, 4), 512, SMEM_TOTAL>>>(x, out);
}

// round 17
// speedup vs baseline: 1.1052x; 1.0142x over previous
#include <cuda_runtime.h>
#include <cuda_fp16.h>

// ---------------------------------------------------------------------------
// DeformableBottleneck: B=16, Cin=O=1024, H=W=32, P=256.
// All convs as fp16 mma.sync GEMMs, fp32 accumulate.
// Unified GEMM shape: 64-row m-tiles, 256 thr (8 warps, 2m x 4n, warp 32x64),
// 3-stage cp.async, 2 CTAs/SM. GEMM2 fuses bilinear sampling (hfma2 combine).
// ---------------------------------------------------------------------------

#define HW 1024
#define CIN 1024
#define PDIM 256
#define ODIM 1024
#define BATCH 16
#define KT 32

typedef unsigned uns;
typedef unsigned short us;

__device__ us    g_hh [BATCH * HW * PDIM];          // h1 fp16, NHWC
__device__ us    g_h2h[BATCH * HW * PDIM];          // h2 fp16
__device__ float g_off[BATCH * 18 * HW];
__device__ us    g_w1h[PDIM * CIN];
__device__ us    g_w2h[PDIM * 9 * PDIM];
__device__ us    g_w3h[ODIM * PDIM];
__device__ us    g_offwT[32 * 9 * PDIM];            // [j(pad32)][tap*256+c]
__device__ float g_s1[PDIM], g_t1[PDIM];
__device__ float g_s2[PDIM], g_t2[PDIM];
__device__ float g_s3[ODIM], g_t3[ODIM];

// unified stage: A 0 (5120; mode1 uses 32x144=4608), B 5120 (20480)
#define OFF_B2 5120
#define G2STG  25600
#define NSTAGE 3
#define SMEM_TOTAL (NSTAGE * G2STG)     // 76800 -> 2 CTAs/SM

// fused GEMM2 adds sampling tables after the 3 stages
#define P_W    (3 * G2STG)              // 76800: 576 * uint4 (dup-half2 weights)
#define P_I    (P_W + 9216)             // 86016: 576 * ushort4 (corner indices)
#define SMEM2_TOTAL (P_I + 4608)        // 90624 -> 2 CTAs/SM

// off_gemm smem stage: A 0 (5120), B 5120 (2560)
#define OFF_OB  5120
#define OSTAGE  7680
#define OSMEM_TOTAL (4 * OSTAGE)        // 30720 B

// ------------------------- PTX helpers -------------------------
__device__ __forceinline__ uns smem_u32(const void* p) {
    uns r;
    asm("{ .reg .u64 t; cvta.to.shared.u64 t, %1; cvt.u32.u64 %0, t; }"
        : "=r"(r) : "l"(p));
    return r;
}
__device__ __forceinline__ void cpa(uns dst, const void* src) {
    asm volatile("cp.async.cg.shared.global [%0], [%1], 16;" :: "r"(dst), "l"(src) : "memory");
}
__device__ __forceinline__ void cpa_z(uns dst, const void* src, uns sz) {
    asm volatile("cp.async.cg.shared.global [%0], [%1], 16, %2;"
                 :: "r"(dst), "l"(src), "r"(sz) : "memory");
}
__device__ __forceinline__ void cpa_commit() {
    asm volatile("cp.async.commit_group;" ::: "memory");
}
template <int N> __device__ __forceinline__ void cpa_wait() {
    asm volatile("cp.async.wait_group %0;" :: "n"(N) : "memory");
}
__device__ __forceinline__ void ldsm4(uns* r, uns a) {
    asm volatile("ldmatrix.sync.aligned.m8n8.x4.shared.b16 {%0,%1,%2,%3}, [%4];"
                 : "=r"(r[0]), "=r"(r[1]), "=r"(r[2]), "=r"(r[3]) : "r"(a));
}
__device__ __forceinline__ void ldsm4t(uns* r, uns a) {
    asm volatile("ldmatrix.sync.aligned.m8n8.x4.trans.shared.b16 {%0,%1,%2,%3}, [%4];"
                 : "=r"(r[0]), "=r"(r[1]), "=r"(r[2]), "=r"(r[3]) : "r"(a));
}
__device__ __forceinline__ void mma_f16(float* d, const uns* a, const uns* b) {
    asm volatile(
        "mma.sync.aligned.m16n8k16.row.col.f32.f16.f16.f32 "
        "{%0,%1,%2,%3}, {%4,%5,%6,%7}, {%8,%9}, {%0,%1,%2,%3};"
        : "+f"(d[0]), "+f"(d[1]), "+f"(d[2]), "+f"(d[3])
        : "r"(a[0]), "r"(a[1]), "r"(a[2]), "r"(a[3]), "r"(b[0]), "r"(b[1]));
}
__device__ __forceinline__ us f2h(float x) {
    return __half_as_ushort(__float2half_rn(x));
}
__device__ __forceinline__ uns pack2h(float a, float b) {
    __half2 h = __floats2half2_rn(a, b);
    return *(uns*)&h;
}
__device__ __forceinline__ __half2 u2h2(uns u) { return *(__half2*)&u; }

// ------------------------- merged prep kernel -------------------------
__global__ void prep_kernel(const float* __restrict__ off_w,
                            const float* __restrict__ w2,
                            const float* __restrict__ w1,
                            const float* __restrict__ w3,
                            const float* __restrict__ g1, const float* __restrict__ b1,
                            const float* __restrict__ m1, const float* __restrict__ v1,
                            const float* __restrict__ g2, const float* __restrict__ b2,
                            const float* __restrict__ m2, const float* __restrict__ v2,
                            const float* __restrict__ g3, const float* __restrict__ b3,
                            const float* __restrict__ m3, const float* __restrict__ v3) {
    int blk = blockIdx.x;
    int tid = threadIdx.x;
    if (blk < 288) {
        int idx = blk * 256 + tid;                  // < 32*2304
        int j = idx / 2304;
        int r = idx % 2304;
        int tap = r >> 8;
        int c = r & 255;
        g_offwT[idx] = (j < 18) ? f2h(off_w[(j * 256 + c) * 9 + tap]) : (us)0;
    } else if (blk < 2592) {
        int idx = (blk - 288) * 256 + tid;          // < 256*2304
        int o = idx / 2304;
        int r = idx % 2304;
        int k = r >> 8;
        int c = r & 255;
        g_w2h[idx] = f2h(w2[(o * 256 + c) * 9 + k]);
    } else if (blk < 2848) {
        int i = (blk - 2592) * 256 + tid;           // < 65536 float4s
        float4 v = ((const float4*)w1)[i];
        ((ushort4*)g_w1h)[i] = make_ushort4(f2h(v.x), f2h(v.y), f2h(v.z), f2h(v.w));
    } else if (blk < 3104) {
        int i = (blk - 2848) * 256 + tid;
        float4 v = ((const float4*)w3)[i];
        ((ushort4*)g_w3h)[i] = make_ushort4(f2h(v.x), f2h(v.y), f2h(v.z), f2h(v.w));
    } else {
        int i = (blk - 3104) * 256 + tid;
        if (i < PDIM) {
            float s = g1[i] / sqrtf(v1[i] + 1e-5f);
            g_s1[i] = s; g_t1[i] = b1[i] - m1[i] * s;
            s = g2[i] / sqrtf(v2[i] + 1e-5f);
            g_s2[i] = s; g_t2[i] = b2[i] - m2[i] * s;
        }
        if (i < ODIM) {
            float s = g3[i] / sqrtf(v3[i] + 1e-5f);
            g_s3[i] = s; g_t3[i] = b3[i] - m3[i] * s;
        }
    }
}

// ------------------------- main tensor-core GEMM (modes 1, 3) ----------------
// 64-row m-tiles, 256 thr. MODE 1: A=x fp32 k-major (cvt in builder), grid 256.
// MODE 3: A=g_h2h, B=w3 n-tile, grid (256,4), out NCHW + bn + residual + relu.
template <int MODE>
__global__ void __launch_bounds__(256, 2) tc_gemm(const float* __restrict__ Xres,
                                                  float* __restrict__ Out) {
    extern __shared__ char ds[];
    constexpr int Ktot = (MODE == 1) ? 1024 : 256;
    constexpr int T = Ktot / KT;

    const int tid = threadIdx.x;
    const int lane = tid & 31;
    const int wid = tid >> 5;
    const int g = lane >> 2;
    const int tq = lane & 3;
    const int mw = wid & 1;          // 2 m groups of 32 rows
    const int nw = wid >> 1;         // 4 n groups of 64 cols
    const int n0 = (MODE == 3) ? blockIdx.y * 256 : 0;

    const us *Ah_g = nullptr, *Bh_g;
    const float* Xf = nullptr;
    int m0 = 0, b_img = 0, hw0 = 0;
    if constexpr (MODE == 1) {
        b_img = blockIdx.x >> 4;
        hw0 = (blockIdx.x & 15) << 6;
        Xf = Xres + (size_t)b_img * (CIN * HW);
        Bh_g = g_w1h;
    } else {
        m0 = blockIdx.x * 64;
        Ah_g = g_h2h;
        Bh_g = g_w3h + (size_t)n0 * Ktot;
    }

    const uns sb = smem_u32(ds);

    auto issueB = [&](int t) {
        const int k0 = t * KT;
        const uns st = sb + (t % NSTAGE) * G2STG;
#pragma unroll
        for (int r = 0; r < 4; r++) {
            int i = tid + 256 * r;
            int row = i >> 2, c = i & 3;
            const us* sh = Bh_g + (size_t)row * Ktot + k0 + c * 8;
            cpa(st + OFF_B2 + row * 80 + c * 16, sh);
        }
        if constexpr (MODE != 1) {
            int row = tid >> 2, c = tid & 3;      // 64 m-rows x 4 chunks
            const us* sh = Ah_g + (size_t)(m0 + row) * Ktot + k0 + c * 8;
            cpa(st + row * 80 + c * 16, sh);
        }
        cpa_commit();
    };
    // MODE 1: synchronous fp32 load + cvt + STS (32 k-rows x 64 m, stride 144)
    auto buildA = [&](int t) {
        if constexpr (MODE == 1) {
            const int k0 = t * KT;
            const uns off = (t % NSTAGE) * G2STG;
            int row = tid >> 3, c = tid & 7;
            const float* src = Xf + (size_t)(k0 + row) * HW + hw0 + c * 8;
            float4 a = *(const float4*)(src);
            float4 b = *(const float4*)(src + 4);
            uint4 o;
            o.x = pack2h(a.x, a.y);
            o.y = pack2h(a.z, a.w);
            o.z = pack2h(b.x, b.y);
            o.w = pack2h(b.z, b.w);
            *(uint4*)(ds + off + row * 144 + c * 16) = o;
        }
    };

    float acc[2][8][4];
#pragma unroll
    for (int i = 0; i < 2; i++)
#pragma unroll
        for (int j = 0; j < 8; j++)
#pragma unroll
            for (int c = 0; c < 4; c++) acc[i][j][c] = 0.0f;

    const int aRow  = (lane & 7) + ((lane >> 3) & 1) * 8;
    const int aColB = (lane >> 4) * 16;
    const int tRow  = (lane & 7) + ((lane >> 4) & 1) * 8;
    const int tColB = ((lane >> 3) & 1) * 16;

    issueB(0); issueB(1);
    buildA(0); buildA(1);

    for (int t = 0; t < T; t++) {
        cpa_wait<1>();
        __syncthreads();
        if (t + 2 < T) { issueB(t + 2); buildA(t + 2); }
        else cpa_commit();
        const uns st = sb + (t % NSTAGE) * G2STG;
#pragma unroll
        for (int kk = 0; kk < 2; kk++) {
            uns ah[2][4], bh[8][2];
#pragma unroll
            for (int mt = 0; mt < 2; mt++) {
                if constexpr (MODE == 1) {
                    uns addr = st + (kk * 16 + tRow) * 144 + (mw * 32 + mt * 16) * 2 + tColB;
                    ldsm4t(ah[mt], addr);
                } else {
                    uns addr = st + (mw * 32 + mt * 16 + aRow) * 80 + kk * 32 + aColB;
                    ldsm4(ah[mt], addr);
                }
            }
#pragma unroll
            for (int p = 0; p < 4; p++) {
                uns r4[4];
                uns addr = st + OFF_B2 + (nw * 64 + p * 16 + aRow) * 80 + kk * 32 + aColB;
                ldsm4(r4, addr);
                bh[2 * p][0] = r4[0]; bh[2 * p + 1][0] = r4[1];
                bh[2 * p][1] = r4[2]; bh[2 * p + 1][1] = r4[3];
            }
#pragma unroll
            for (int mt = 0; mt < 2; mt++)
#pragma unroll
                for (int nt = 0; nt < 8; nt++)
                    mma_f16(acc[mt][nt], ah[mt], bh[nt]);
        }
    }

    // ---------------- epilogue ----------------
    if constexpr (MODE == 3) {
        float* Cs = (float*)ds;   // [128 n][66] per half
        int bb = m0 >> 10;
        int hwb = m0 & 1023;
        size_t obase = ((size_t)bb << 20) + hwb;
#pragma unroll
        for (int half = 0; half < 2; half++) {
            __syncthreads();
            if ((nw >> 1) == half) {
                int colbase = (nw & 1) * 64;
#pragma unroll
                for (int mt = 0; mt < 2; mt++) {
#pragma unroll
                    for (int nt = 0; nt < 8; nt++) {
                        int row = mw * 32 + mt * 16 + g;
                        int col = colbase + nt * 8 + 2 * tq;
                        Cs[(col)     * 66 + row]     = acc[mt][nt][0];
                        Cs[(col + 1) * 66 + row]     = acc[mt][nt][1];
                        Cs[(col)     * 66 + row + 8] = acc[mt][nt][2];
                        Cs[(col + 1) * 66 + row + 8] = acc[mt][nt][3];
                    }
                }
            }
            __syncthreads();
#pragma unroll
            for (int i = 0; i < 32; i++) {
                int idx = i * 256 + tid;
                int nl = idx >> 6;
                int ml = idx & 63;
                int n = n0 + half * 128 + nl;
                float v = fmaf(Cs[nl * 66 + ml], g_s3[n], g_t3[n]);
                size_t addr = obase + ((size_t)n << 10) + ml;
                v += Xres[addr];
                Out[addr] = fmaxf(v, 0.0f);
            }
        }
    } else {
        us* dh = g_hh + ((size_t)((b_img << 10) + hw0)) * 256;
#pragma unroll
        for (int mt = 0; mt < 2; mt++) {
#pragma unroll
            for (int nt = 0; nt < 8; nt++) {
                int row = mw * 32 + mt * 16 + g;
                int col = nw * 64 + nt * 8 + 2 * tq;
                float s0 = g_s1[col], t0 = g_t1[col];
                float s1 = g_s1[col + 1], t1 = g_t1[col + 1];
                float v0 = fmaxf(fmaf(acc[mt][nt][0], s0, t0), 0.0f);
                float v1 = fmaxf(fmaf(acc[mt][nt][1], s1, t1), 0.0f);
                float v2 = fmaxf(fmaf(acc[mt][nt][2], s0, t0), 0.0f);
                float v3 = fmaxf(fmaf(acc[mt][nt][3], s1, t1), 0.0f);
                *(uns*)(dh + (size_t)row * 256 + col) = (uns)f2h(v0) | ((uns)f2h(v1) << 16);
                *(uns*)(dh + (size_t)(row + 8) * 256 + col) = (uns)f2h(v2) | ((uns)f2h(v3) << 16);
            }
        }
    }
}

// ------------------------- fused sampler + GEMM2 -------------------------
// C[m][n=256] = S[m][k=2304] @ w2t[n][k]; 64-row m-tiles, grid 256,
// 256 threads (8 warps: 2m x 4n, warp tile 32x64), 2 CTAs/SM.
__global__ void __launch_bounds__(256, 2) tc_gemm2_f() {
    extern __shared__ char ds[];
    const int tid = threadIdx.x;
    const int lane = tid & 31;
    const int wid = tid >> 5;
    const int g = lane >> 2;
    const int tq = lane & 3;
    const int mw = wid & 1;
    const int nw = wid >> 1;
    const int m0 = blockIdx.x * 64;
    const int b_img = m0 >> 10;
    const int hw0 = m0 & 1023;
    const uns sb = smem_u32(ds);
    const us* hbase = g_hh + ((size_t)b_img << 18);

    // ---- setup: sampling table for 64 rows x 9 taps ----
    for (int it = tid; it < 576; it += 256) {
        int row = it / 9;
        int k = it - row * 9;
        int hw = hw0 + row;
        int y = hw >> 5, x = hw & 31;
        float oy = g_off[((b_img * 18 + 2 * k) << 10) + hw];
        float ox = g_off[((b_img * 18 + 2 * k + 1) << 10) + hw];
        float py = (float)(y + k / 3 - 1) + oy;
        float px = (float)(x + k % 3 - 1) + ox;
        float y0f = floorf(py), x0f = floorf(px);
        float wy = py - y0f, wx = px - x0f;
        int y0 = (int)y0f, x0 = (int)x0f;
        int y1 = y0 + 1, x1 = x0 + 1;
        float vy0 = (y0 >= 0 && y0 <= 31) ? 1.0f : 0.0f;
        float vy1 = (y1 >= 0 && y1 <= 31) ? 1.0f : 0.0f;
        float vx0 = (x0 >= 0 && x0 <= 31) ? 1.0f : 0.0f;
        float vx1 = (x1 >= 0 && x1 <= 31) ? 1.0f : 0.0f;
        float w00 = (1.0f - wy) * (1.0f - wx) * vy0 * vx0;
        float w01 = (1.0f - wy) * wx * vy0 * vx1;
        float w10 = wy * (1.0f - wx) * vy1 * vx0;
        float w11 = wy * wx * vy1 * vx1;
        int y0c = min(max(y0, 0), 31), y1c = min(max(y1, 0), 31);
        int x0c = min(max(x0, 0), 31), x1c = min(max(x1, 0), 31);
        *(uint4*)(ds + P_W + it * 16) =
            make_uint4(pack2h(w00, w00), pack2h(w01, w01),
                       pack2h(w10, w10), pack2h(w11, w11));
        *(ushort4*)(ds + P_I + it * 8) =
            make_ushort4((us)(y0c * 32 + x0c), (us)(y0c * 32 + x1c),
                         (us)(y1c * 32 + x0c), (us)(y1c * 32 + x1c));
    }

    const int arow = tid >> 2;     // A loader: 64 rows x 4 chunks
    const int ac = tid & 3;

    auto issueB = [&](int t) {
        const int k0 = t * KT;
        const uns st = sb + (t % 3) * G2STG;
#pragma unroll
        for (int r = 0; r < 4; r++) {
            int i = tid + 256 * r;
            int row = i >> 2, c = i & 3;
            cpa(st + OFF_B2 + row * 80 + c * 16, g_w2h + (size_t)row * 2304 + k0 + c * 8);
        }
        cpa_commit();
    };

    auto ldgA = [&](int t, uint4& wq, uint4& q0, uint4& q1, uint4& q2, uint4& q3) {
        const int k0 = t * KT;
        const int tap = k0 >> 8;
        const int c0 = (k0 & 255) + ac * 8;
        int it = arow * 9 + tap;
        wq = *(const uint4*)(ds + P_W + it * 16);
        ushort4 iv = *(const ushort4*)(ds + P_I + it * 8);
        q0 = *(const uint4*)(hbase + ((int)iv.x << 8) + c0);
        q1 = *(const uint4*)(hbase + ((int)iv.y << 8) + c0);
        q2 = *(const uint4*)(hbase + ((int)iv.z << 8) + c0);
        q3 = *(const uint4*)(hbase + ((int)iv.w << 8) + c0);
    };
    auto stsA = [&](int t, uint4 wq, uint4 q0, uint4 q1, uint4 q2, uint4 q3) {
        const uns* a0 = (const uns*)&q0;
        const uns* a1 = (const uns*)&q1;
        const uns* a2 = (const uns*)&q2;
        const uns* a3 = (const uns*)&q3;
        uint4 o;
#pragma unroll
        for (int j = 0; j < 4; j++) {
            __half2 v = __hmul2(u2h2(a0[j]), u2h2(wq.x));
            v = __hfma2(u2h2(a1[j]), u2h2(wq.y), v);
            v = __hfma2(u2h2(a2[j]), u2h2(wq.z), v);
            v = __hfma2(u2h2(a3[j]), u2h2(wq.w), v);
            ((uns*)&o)[j] = *(uns*)&v;
        }
        *(uint4*)(ds + (t % 3) * G2STG + arow * 80 + ac * 16) = o;
    };

    float acc[2][8][4];
#pragma unroll
    for (int i = 0; i < 2; i++)
#pragma unroll
        for (int j = 0; j < 8; j++)
#pragma unroll
            for (int c = 0; c < 4; c++) acc[i][j][c] = 0.0f;

    const int aRow  = (lane & 7) + ((lane >> 3) & 1) * 8;
    const int aColB = (lane >> 4) * 16;

    issueB(0); issueB(1);
    __syncthreads();             // sampling table ready
    {
        uint4 wq, q0, q1, q2, q3;
        ldgA(0, wq, q0, q1, q2, q3);
        stsA(0, wq, q0, q1, q2, q3);
    }

    const int T = 2304 / KT;     // 72
    for (int t = 0; t < T; t++) {
        cpa_wait<1>();
        __syncthreads();
        if (t + 2 < T) issueB(t + 2); else cpa_commit();
        uint4 wq, q0, q1, q2, q3;
        const bool have = (t + 1 < T);
        if (have) ldgA(t + 1, wq, q0, q1, q2, q3);
        const uns st = sb + (t % 3) * G2STG;
#pragma unroll
        for (int kk = 0; kk < 2; kk++) {
            uns ah[2][4], bh[8][2];
#pragma unroll
            for (int mt = 0; mt < 2; mt++) {
                uns addr = st + (mw * 32 + mt * 16 + aRow) * 80 + kk * 32 + aColB;
                ldsm4(ah[mt], addr);
            }
#pragma unroll
            for (int p = 0; p < 4; p++) {
                uns r4[4];
                uns addr = st + OFF_B2 + (nw * 64 + p * 16 + aRow) * 80 + kk * 32 + aColB;
                ldsm4(r4, addr);
                bh[2 * p][0] = r4[0]; bh[2 * p + 1][0] = r4[1];
                bh[2 * p][1] = r4[2]; bh[2 * p + 1][1] = r4[3];
            }
#pragma unroll
            for (int mt = 0; mt < 2; mt++)
#pragma unroll
                for (int nt = 0; nt < 8; nt++)
                    mma_f16(acc[mt][nt], ah[mt], bh[nt]);
        }
        if (have) stsA(t + 1, wq, q0, q1, q2, q3);
    }

    // epilogue -> g_h2h (+bn2+relu)
    us* dh = g_h2h + (size_t)m0 * 256;
#pragma unroll
    for (int mt = 0; mt < 2; mt++) {
#pragma unroll
        for (int nt = 0; nt < 8; nt++) {
            int row = mw * 32 + mt * 16 + g;
            int col = nw * 64 + nt * 8 + 2 * tq;
            float s0 = g_s2[col], t0 = g_t2[col];
            float s1 = g_s2[col + 1], t1 = g_t2[col + 1];
            float v0 = fmaxf(fmaf(acc[mt][nt][0], s0, t0), 0.0f);
            float v1 = fmaxf(fmaf(acc[mt][nt][1], s1, t1), 0.0f);
            float v2 = fmaxf(fmaf(acc[mt][nt][2], s0, t0), 0.0f);
            float v3 = fmaxf(fmaf(acc[mt][nt][3], s1, t1), 0.0f);
            *(uns*)(dh + (size_t)row * 256 + col) = (uns)f2h(v0) | ((uns)f2h(v1) << 16);
            *(uns*)(dh + (size_t)(row + 8) * 256 + col) = (uns)f2h(v2) | ((uns)f2h(v3) << 16);
        }
    }
}

// ------------------------- offset conv as GEMM -------------------------
__global__ void __launch_bounds__(128, 4) off_gemm(const float* __restrict__ off_b) {
    extern __shared__ char ds[];
    const int tid = threadIdx.x;
    const int lane = tid & 31;
    const int wid = tid >> 5;
    const int g = lane >> 2;
    const int tq = lane & 3;
    const int m0 = blockIdx.x * 64;
    const int b_img = m0 >> 10;
    const int hw0 = m0 & 1023;
    const uns sb = smem_u32(ds);

    auto issue = [&](int t) {
        const int k0 = t * KT;
        const int tap = k0 >> 8;
        const int c0 = k0 & 255;
        const int dy = tap / 3 - 1, dx = tap % 3 - 1;
        const uns st = sb + (t & 3) * OSTAGE;
        {
            int row = tid >> 2, c = tid & 3;
            const us* src = g_offwT + row * 2304 + k0 + c * 8;
            cpa(st + OFF_OB + row * 80 + c * 16, src);
        }
#pragma unroll
        for (int r = 0; r < 2; r++) {
            int i = tid + 128 * r;
            int row = i >> 2, c = i & 3;
            int hw = hw0 + row;
            int y = hw >> 5, x = hw & 31;
            int yy = y + dy, xx = x + dx;
            uns ok = (yy >= 0 && yy < 32 && xx >= 0 && xx < 32) ? 16u : 0u;
            int yc = min(max(yy, 0), 31), xc = min(max(xx, 0), 31);
            const us* src = g_hh + ((size_t)((b_img << 10) + (yc << 5) + xc)) * 256 + c0 + c * 8;
            cpa_z(st + row * 80 + c * 16, src, ok);
        }
        cpa_commit();
    };

    float acc[4][4];
#pragma unroll
    for (int j = 0; j < 4; j++)
#pragma unroll
        for (int c = 0; c < 4; c++) acc[j][c] = 0.0f;

    const int aRow  = (lane & 7) + ((lane >> 3) & 1) * 8;
    const int aColB = (lane >> 4) * 16;

    issue(0); issue(1); issue(2);

    const int T = 2304 / KT;   // 72
    for (int t = 0; t < T; t++) {
        cpa_wait<2>();
        __syncthreads();
        if (t + 3 < T) issue(t + 3); else cpa_commit();
        const uns st = sb + (t & 3) * OSTAGE;
#pragma unroll
        for (int kk = 0; kk < 2; kk++) {
            uns ah[4], bh[4][2];
            {
                uns addr = st + (wid * 16 + aRow) * 80 + kk * 32 + aColB;
                ldsm4(ah, addr);
            }
#pragma unroll
            for (int p = 0; p < 2; p++) {
                uns r4[4];
                uns addr = st + OFF_OB + (p * 16 + aRow) * 80 + kk * 32 + aColB;
                ldsm4(r4, addr);
                bh[2 * p][0] = r4[0]; bh[2 * p + 1][0] = r4[1];
                bh[2 * p][1] = r4[2]; bh[2 * p + 1][1] = r4[3];
            }
#pragma unroll
            for (int nt = 0; nt < 4; nt++)
                mma_f16(acc[nt], ah, bh[nt]);
        }
        __syncthreads();
    }

    float* dst = g_off + (size_t)b_img * (18 * HW) + hw0;
#pragma unroll
    for (int nt = 0; nt < 4; nt++) {
        int col = nt * 8 + 2 * tq;
        int row = wid * 16 + g;
        if (col < 18) {
            float bb = off_b[col];
            dst[col * HW + row] = acc[nt][0] + bb;
            dst[col * HW + row + 8] = acc[nt][2] + bb;
        }
        if (col + 1 < 18) {
            float bb = off_b[col + 1];
            dst[(col + 1) * HW + row] = acc[nt][1] + bb;
            dst[(col + 1) * HW + row + 8] = acc[nt][3] + bb;
        }
    }
}

// ------------------------- launcher -------------------------
extern "C" void kernel_launch(void* const* d_in, const int* in_sizes, int n_in,
                              void* d_out, int out_size) {
    const float* x     = (const float*)d_in[0];
    const float* w1    = (const float*)d_in[1];
    const float* bn1g  = (const float*)d_in[2];
    const float* bn1b  = (const float*)d_in[3];
    const float* bn1m  = (const float*)d_in[4];
    const float* bn1v  = (const float*)d_in[5];
    const float* off_w = (const float*)d_in[6];
    const float* off_b = (const float*)d_in[7];
    const float* w2    = (const float*)d_in[8];
    const float* bn2g  = (const float*)d_in[9];
    const float* bn2b  = (const float*)d_in[10];
    const float* bn2m  = (const float*)d_in[11];
    const float* bn2v  = (const float*)d_in[12];
    const float* w3    = (const float*)d_in[13];
    const float* bn3g  = (const float*)d_in[14];
    const float* bn3b  = (const float*)d_in[15];
    const float* bn3m  = (const float*)d_in[16];
    const float* bn3v  = (const float*)d_in[17];
    float* out = (float*)d_out;

    cudaFuncSetAttribute(tc_gemm<1>, cudaFuncAttributeMaxDynamicSharedMemorySize, SMEM_TOTAL);
    cudaFuncSetAttribute(tc_gemm<3>, cudaFuncAttributeMaxDynamicSharedMemorySize, SMEM_TOTAL);
    cudaFuncSetAttribute(tc_gemm2_f, cudaFuncAttributeMaxDynamicSharedMemorySize, SMEM2_TOTAL);
    cudaFuncSetAttribute(off_gemm, cudaFuncAttributeMaxDynamicSharedMemorySize, OSMEM_TOTAL);

    prep_kernel<<<3108, 256>>>(off_w, w2, w1, w3,
                               bn1g, bn1b, bn1m, bn1v,
                               bn2g, bn2b, bn2m, bn2v,
                               bn3g, bn3b, bn3m, bn3v);
    tc_gemm<1><<<256, 256, SMEM_TOTAL>>>(x, nullptr);
    off_gemm<<<256, 128, OSMEM_TOTAL>>>(off_b);
    tc_gemm2_f<<<256, 256, SMEM2_TOTAL>>>();
    tc_gemm<3><<<dim3(256, 4), 256, SMEM_TOTAL>>>(x, out);  // profiled slot
}